// round 6
// baseline (speedup 1.0000x reference)
#include <cuda_runtime.h>
#include <cuda_fp16.h>

// WindowAttention: fp16 m16n8k16 mma GEMMs + fp32 attention, fused buffers.
// 50176 windows of [16 tok, 96 ch], H=8, D=12. Persistent CTAs, 8 warps.
// Per tile: 8 windows. GEMM warps = (window-quad mp, chunk-quarter cs).
// QS[128][292]: cols 0-95 Q (overwritten in place by attn-out), 96-191 K, 192-287 V.

#define NWIN   50176
#define NTILES (NWIN / 8)      // 6272
#define L_DIM  3136
#define SCALE  0.28867513459481287f
#define QSTR   292             // QS row stride (floats)

// SMEM layout (bytes)
#define OFF_PQ   0             // QKV B-pack fp16: 36cq*6ks*32ln*2u32 = 55296
#define OFF_QS   55296         // [128][292] f32 = 149504
#define OFF_PRJ  204800        // proj B-pack fp16: 12*6*64 u32 = 18432
#define OFF_BQ   223232        // qkv_bias 288 f
#define OFF_BP   224384        // proj_bias 96 f
#define SMEM_BYTES 224768

typedef unsigned int u32;

__device__ float RBG[4 * 16 * 2 * 16];   // rel-bias [hp][ti][hsel][j], L1-cached

__device__ __forceinline__ u32 p16(float a, float b) {
    __half2 h = __floats2half2_rn(a, b);
    return *(u32*)&h;
}
__device__ __forceinline__ void mma16(float& c0, float& c1, float& c2, float& c3,
                                      u32 a0, u32 a1, u32 a2, u32 a3,
                                      u32 b0, u32 b1) {
    asm volatile(
        "mma.sync.aligned.m16n8k16.row.col.f32.f16.f16.f32 "
        "{%0,%1,%2,%3}, {%4,%5,%6,%7}, {%8,%9}, {%0,%1,%2,%3};"
        : "+f"(c0), "+f"(c1), "+f"(c2), "+f"(c3)
        : "r"(a0), "r"(a1), "r"(a2), "r"(a3), "r"(b0), "r"(b1));
}

__global__ __launch_bounds__(256, 1)
void win_attn_kernel(const float* __restrict__ x,
                     const float* __restrict__ mask,
                     const float* __restrict__ qkv_w,
                     const float* __restrict__ qkv_b,
                     const float* __restrict__ proj_w,
                     const float* __restrict__ proj_b,
                     const float* __restrict__ bias_table,
                     float* __restrict__ out)
{
    extern __shared__ char smb[];
    u32*   PQs  = (u32*)(smb + OFF_PQ);
    float* QSf  = (float*)(smb + OFF_QS);
    u32*   PRJs = (u32*)(smb + OFF_PRJ);
    float* BQs  = (float*)(smb + OFF_BQ);
    float* BPs  = (float*)(smb + OFF_BP);

    const int t = threadIdx.x;

    // ---- One-time staging ----
    // QKV B-pack: b0={W[k0][n],W[k0+1][n]}, b1={W[k0+8][n],W[k0+9][n]} fp16
    for (int i = t; i < 36 * 6 * 32; i += 256) {
        int cq = i / 192, r = i % 192, ks = r / 32, lnn = r % 32;
        int gi = lnn >> 2, tg = lnn & 3;
        int k0 = ks * 16 + 2 * tg, n = cq * 8 + gi;
        PQs[i * 2 + 0] = p16(qkv_w[k0 * 288 + n],       qkv_w[(k0 + 1) * 288 + n]);
        PQs[i * 2 + 1] = p16(qkv_w[(k0 + 8) * 288 + n], qkv_w[(k0 + 9) * 288 + n]);
    }
    // proj B-pack
    for (int i = t; i < 12 * 6 * 32; i += 256) {
        int cq = i / 192, r = i % 192, ks = r / 32, lnn = r % 32;
        int gi = lnn >> 2, tg = lnn & 3;
        int k0 = ks * 16 + 2 * tg, n = cq * 8 + gi;
        PRJs[i * 2 + 0] = p16(proj_w[k0 * 96 + n],       proj_w[(k0 + 1) * 96 + n]);
        PRJs[i * 2 + 1] = p16(proj_w[(k0 + 8) * 96 + n], proj_w[(k0 + 9) * 96 + n]);
    }
    // rel-bias expanded table -> global (all CTAs write identical values)
    for (int i = t; i < 2048; i += 256) {
        int hp = i >> 9, ti = (i >> 5) & 15, hsel = (i >> 4) & 1, j = i & 15;
        int h  = 2 * hp + hsel;
        int d0 = (ti & 3)  - (j & 3)  + 3;
        int d1 = (ti >> 2) - (j >> 2) + 3;
        RBG[i] = bias_table[(d0 * 7 + d1) * 8 + h];
    }
    for (int i = t; i < 288; i += 256) BQs[i] = qkv_b[i];
    if (t < 96) BPs[t] = proj_b[t];
    __syncthreads();

    const int wid = t >> 5;
    const int ln  = t & 31;
    const int gi  = ln >> 2;        // fragment row 0..7
    const int tg  = ln & 3;         // fragment col group
    const int mp  = wid >> 2;       // window quad 0..1 (windows 4mp..4mp+3)
    const int cs  = wid & 3;        // chunk quarter
    // attention identity
    const int aw   = wid;           // warp = window
    const int hsel = (t >> 4) & 1;
    const int ti   = t & 15;

    for (int g = blockIdx.x; g < NTILES; g += gridDim.x) {
        // ================= QKV GEMM =================
        {
            // A fragments: 4 windows x 6 ksteps x 4 regs (fp16 pairs)
            u32 af[4][6][4];
            #pragma unroll
            for (int wd = 0; wd < 4; wd++) {
                const float* xr = x + ((size_t)g * 128 + (mp * 4 + wd) * 16 + gi) * 96;
                #pragma unroll
                for (int ks = 0; ks < 6; ks++) {
                    float2 v0 = *(const float2*)(xr + ks * 16 + 2 * tg);
                    float2 v1 = *(const float2*)(xr + 768 + ks * 16 + 2 * tg);
                    float2 v2 = *(const float2*)(xr + ks * 16 + 2 * tg + 8);
                    float2 v3 = *(const float2*)(xr + 768 + ks * 16 + 2 * tg + 8);
                    af[wd][ks][0] = p16(v0.x, v0.y);
                    af[wd][ks][1] = p16(v1.x, v1.y);
                    af[wd][ks][2] = p16(v2.x, v2.y);
                    af[wd][ks][3] = p16(v3.x, v3.y);
                }
            }
            // 9 chunks of 8 output cols each (this warp's quarter of 36)
            #pragma unroll 1
            for (int j = 0; j < 9; j++) {
                const int cq = cs * 9 + j;
                float2 bb = *(const float2*)&BQs[cq * 8 + 2 * tg];
                float c[4][4];
                #pragma unroll
                for (int wd = 0; wd < 4; wd++) {
                    c[wd][0] = bb.x; c[wd][1] = bb.y;
                    c[wd][2] = bb.x; c[wd][3] = bb.y;
                }
                const u32* bp = PQs + (size_t)cq * 384 + ln * 2;
                #pragma unroll
                for (int ks = 0; ks < 6; ks++) {
                    u32 b0 = bp[ks * 64], b1 = bp[ks * 64 + 1];
                    #pragma unroll
                    for (int wd = 0; wd < 4; wd++)
                        mma16(c[wd][0], c[wd][1], c[wd][2], c[wd][3],
                              af[wd][ks][0], af[wd][ks][1], af[wd][ks][2], af[wd][ks][3],
                              b0, b1);
                }
                #pragma unroll
                for (int wd = 0; wd < 4; wd++) {
                    float* qr = &QSf[((mp * 4 + wd) * 16 + gi) * QSTR + cq * 8 + 2 * tg];
                    *(float2*)qr                = make_float2(c[wd][0], c[wd][1]);
                    *(float2*)(qr + 8 * QSTR)   = make_float2(c[wd][2], c[wd][3]);
                }
            }
        }
        __syncthreads();

        // ================= Attention (no internal syncs) =================
        {
            const int arow = aw * 16 + ti;
            float m[16];
            {
                const float4* mpt = (const float4*)(mask +
                    (size_t)((g * 8 + aw) % L_DIM) * 256 + ti * 16);
                float4 m0 = mpt[0], m1 = mpt[1], m2 = mpt[2], m3 = mpt[3];
                m[0]=m0.x; m[1]=m0.y; m[2]=m0.z; m[3]=m0.w;
                m[4]=m1.x; m[5]=m1.y; m[6]=m1.z; m[7]=m1.w;
                m[8]=m2.x; m[9]=m2.y; m[10]=m2.z; m[11]=m2.w;
                m[12]=m3.x; m[13]=m3.y; m[14]=m3.z; m[15]=m3.w;
            }
            #pragma unroll 1
            for (int hp = 0; hp < 4; hp++) {
                const int h = 2 * hp + hsel;
                const float4* qp = (const float4*)&QSf[arow * QSTR + h * 12];
                float4 q0 = qp[0], q1 = qp[1], q2 = qp[2];
                float q[12] = { q0.x*SCALE, q0.y*SCALE, q0.z*SCALE, q0.w*SCALE,
                                q1.x*SCALE, q1.y*SCALE, q1.z*SCALE, q1.w*SCALE,
                                q2.x*SCALE, q2.y*SCALE, q2.z*SCALE, q2.w*SCALE };
                const float* rb = RBG + hp * 512 + ti * 32 + hsel * 16;
                float sc[16];
                #pragma unroll
                for (int j = 0; j < 16; j++) {
                    const float4* kk = (const float4*)&QSf[(aw * 16 + j) * QSTR + 96 + h * 12];
                    float4 k0 = kk[0], k1 = kk[1], k2 = kk[2];
                    float s = __ldg(rb + j) + m[j];
                    s += q[0]*k0.x + q[1]*k0.y + q[2] *k0.z + q[3] *k0.w
                       + q[4]*k1.x + q[5]*k1.y + q[6] *k1.z + q[7] *k1.w
                       + q[8]*k2.x + q[9]*k2.y + q[10]*k2.z + q[11]*k2.w;
                    sc[j] = s;
                }
                float mx = sc[0];
                #pragma unroll
                for (int j = 1; j < 16; j++) mx = fmaxf(mx, sc[j]);
                float sum = 0.f;
                #pragma unroll
                for (int j = 0; j < 16; j++) { sc[j] = __expf(sc[j] - mx); sum += sc[j]; }
                float inv = __fdividef(1.f, sum);

                float o[12];
                #pragma unroll
                for (int d = 0; d < 12; d++) o[d] = 0.f;
                #pragma unroll
                for (int j = 0; j < 16; j++) {
                    const float4* vv = (const float4*)&QSf[(aw * 16 + j) * QSTR + 192 + h * 12];
                    float4 v0 = vv[0], v1 = vv[1], v2 = vv[2];
                    float p = sc[j];
                    o[0] += p*v0.x; o[1] += p*v0.y; o[2]  += p*v0.z; o[3]  += p*v0.w;
                    o[4] += p*v1.x; o[5] += p*v1.y; o[6]  += p*v1.z; o[7]  += p*v1.w;
                    o[8] += p*v2.x; o[9] += p*v2.y; o[10] += p*v2.z; o[11] += p*v2.w;
                }
                // overwrite own Q cells in place (out col == Q col)
                float* op = &QSf[arow * QSTR + h * 12];
                ((float4*)op)[0] = make_float4(o[0]*inv, o[1]*inv, o[2]*inv, o[3]*inv);
                ((float4*)op)[1] = make_float4(o[4]*inv, o[5]*inv, o[6]*inv, o[7]*inv);
                ((float4*)op)[2] = make_float4(o[8]*inv, o[9]*inv, o[10]*inv, o[11]*inv);
            }
        }
        __syncthreads();

        // ================= Proj GEMM =================
        {
            u32 pf[4][6][4];
            #pragma unroll
            for (int wd = 0; wd < 4; wd++) {
                const float* orow = &QSf[((mp * 4 + wd) * 16 + gi) * QSTR];
                #pragma unroll
                for (int ks = 0; ks < 6; ks++) {
                    float2 v0 = *(const float2*)(orow + ks * 16 + 2 * tg);
                    float2 v1 = *(const float2*)(orow + 8 * QSTR + ks * 16 + 2 * tg);
                    float2 v2 = *(const float2*)(orow + ks * 16 + 2 * tg + 8);
                    float2 v3 = *(const float2*)(orow + 8 * QSTR + ks * 16 + 2 * tg + 8);
                    pf[wd][ks][0] = p16(v0.x, v0.y);
                    pf[wd][ks][1] = p16(v1.x, v1.y);
                    pf[wd][ks][2] = p16(v2.x, v2.y);
                    pf[wd][ks][3] = p16(v3.x, v3.y);
                }
            }
            #pragma unroll 1
            for (int j = 0; j < 3; j++) {
                const int cq = cs * 3 + j;
                float2 bb = *(const float2*)&BPs[cq * 8 + 2 * tg];
                float c[4][4];
                #pragma unroll
                for (int wd = 0; wd < 4; wd++) {
                    c[wd][0] = bb.x; c[wd][1] = bb.y;
                    c[wd][2] = bb.x; c[wd][3] = bb.y;
                }
                const u32* bp = PRJs + (size_t)cq * 384 + ln * 2;
                #pragma unroll
                for (int ks = 0; ks < 6; ks++) {
                    u32 b0 = bp[ks * 64], b1 = bp[ks * 64 + 1];
                    #pragma unroll
                    for (int wd = 0; wd < 4; wd++)
                        mma16(c[wd][0], c[wd][1], c[wd][2], c[wd][3],
                              pf[wd][ks][0], pf[wd][ks][1], pf[wd][ks][2], pf[wd][ks][3],
                              b0, b1);
                }
                #pragma unroll
                for (int wd = 0; wd < 4; wd++) {
                    float* og = out + ((size_t)g * 128 + (mp * 4 + wd) * 16 + gi) * 96
                                    + cq * 8 + 2 * tg;
                    *(float2*)og              = make_float2(c[wd][0], c[wd][1]);
                    *(float2*)(og + 8 * 96)   = make_float2(c[wd][2], c[wd][3]);
                }
            }
        }
        __syncthreads();   // QS reuse by next tile's GEMM
    }
}

extern "C" void kernel_launch(void* const* d_in, const int* in_sizes, int n_in,
                              void* d_out, int out_size)
{
    const float* x          = (const float*)d_in[0];
    const float* mask       = (const float*)d_in[1];
    const float* qkv_w      = (const float*)d_in[2];
    const float* qkv_b      = (const float*)d_in[3];
    const float* proj_w     = (const float*)d_in[4];
    const float* proj_b     = (const float*)d_in[5];
    const float* bias_table = (const float*)d_in[6];
    float* out = (float*)d_out;

    int sms = 148;
    cudaDeviceGetAttribute(&sms, cudaDevAttrMultiProcessorCount, 0);
    cudaFuncSetAttribute(win_attn_kernel,
                         cudaFuncAttributeMaxDynamicSharedMemorySize, SMEM_BYTES);

    win_attn_kernel<<<sms, 256, SMEM_BYTES>>>(x, mask, qkv_w, qkv_b,
                                              proj_w, proj_b, bias_table, out);
}

// round 7
// speedup vs baseline: 1.0019x; 1.0019x over previous
#include <cuda_runtime.h>
#include <cuda_fp16.h>

// WindowAttention: fp16 m16n8k16 mma GEMMs + fp32 attention, fused buffers.
// 50176 windows of [16 tok, 96 ch], H=8, D=12. Persistent CTAs, 8 warps.
// Per tile: 8 windows. GEMM warps = (window-quad mp, chunk-quarter cs).
// QS[128][292]: cols 0-95 Q (overwritten in place by attn-out), 96-191 K, 192-287 V.

#define NWIN   50176
#define NTILES (NWIN / 8)      // 6272
#define L_DIM  3136
#define SCALE  0.28867513459481287f
#define QSTR   292             // QS row stride (floats)

// SMEM layout (bytes)
#define OFF_PQ   0             // QKV B-pack fp16: 36cq*6ks*32ln*2u32 = 55296
#define OFF_QS   55296         // [128][292] f32 = 149504
#define OFF_PRJ  204800        // proj B-pack fp16: 12*6*64 u32 = 18432
#define OFF_BQ   223232        // qkv_bias 288 f
#define OFF_BP   224384        // proj_bias 96 f
#define SMEM_BYTES 224768

typedef unsigned int u32;

__device__ float RBG[4 * 16 * 2 * 16];   // rel-bias [hp][ti][hsel][j], L1-cached

__device__ __forceinline__ u32 p16(float a, float b) {
    __half2 h = __floats2half2_rn(a, b);
    return *(u32*)&h;
}
__device__ __forceinline__ void mma16(float& c0, float& c1, float& c2, float& c3,
                                      u32 a0, u32 a1, u32 a2, u32 a3,
                                      u32 b0, u32 b1) {
    asm volatile(
        "mma.sync.aligned.m16n8k16.row.col.f32.f16.f16.f32 "
        "{%0,%1,%2,%3}, {%4,%5,%6,%7}, {%8,%9}, {%0,%1,%2,%3};"
        : "+f"(c0), "+f"(c1), "+f"(c2), "+f"(c3)
        : "r"(a0), "r"(a1), "r"(a2), "r"(a3), "r"(b0), "r"(b1));
}

__global__ __launch_bounds__(256, 1)
void win_attn_kernel(const float* __restrict__ x,
                     const float* __restrict__ mask,
                     const float* __restrict__ qkv_w,
                     const float* __restrict__ qkv_b,
                     const float* __restrict__ proj_w,
                     const float* __restrict__ proj_b,
                     const float* __restrict__ bias_table,
                     float* __restrict__ out)
{
    extern __shared__ char smb[];
    u32*   PQs  = (u32*)(smb + OFF_PQ);
    float* QSf  = (float*)(smb + OFF_QS);
    u32*   PRJs = (u32*)(smb + OFF_PRJ);
    float* BQs  = (float*)(smb + OFF_BQ);
    float* BPs  = (float*)(smb + OFF_BP);

    const int t = threadIdx.x;

    // ---- One-time staging ----
    // QKV B-pack: b0={W[k0][n],W[k0+1][n]}, b1={W[k0+8][n],W[k0+9][n]} fp16
    for (int i = t; i < 36 * 6 * 32; i += 256) {
        int cq = i / 192, r = i % 192, ks = r / 32, lnn = r % 32;
        int gi = lnn >> 2, tg = lnn & 3;
        int k0 = ks * 16 + 2 * tg, n = cq * 8 + gi;
        PQs[i * 2 + 0] = p16(qkv_w[k0 * 288 + n],       qkv_w[(k0 + 1) * 288 + n]);
        PQs[i * 2 + 1] = p16(qkv_w[(k0 + 8) * 288 + n], qkv_w[(k0 + 9) * 288 + n]);
    }
    // proj B-pack
    for (int i = t; i < 12 * 6 * 32; i += 256) {
        int cq = i / 192, r = i % 192, ks = r / 32, lnn = r % 32;
        int gi = lnn >> 2, tg = lnn & 3;
        int k0 = ks * 16 + 2 * tg, n = cq * 8 + gi;
        PRJs[i * 2 + 0] = p16(proj_w[k0 * 96 + n],       proj_w[(k0 + 1) * 96 + n]);
        PRJs[i * 2 + 1] = p16(proj_w[(k0 + 8) * 96 + n], proj_w[(k0 + 9) * 96 + n]);
    }
    // rel-bias expanded table -> global (all CTAs write identical values)
    for (int i = t; i < 2048; i += 256) {
        int hp = i >> 9, ti = (i >> 5) & 15, hsel = (i >> 4) & 1, j = i & 15;
        int h  = 2 * hp + hsel;
        int d0 = (ti & 3)  - (j & 3)  + 3;
        int d1 = (ti >> 2) - (j >> 2) + 3;
        RBG[i] = bias_table[(d0 * 7 + d1) * 8 + h];
    }
    for (int i = t; i < 288; i += 256) BQs[i] = qkv_b[i];
    if (t < 96) BPs[t] = proj_b[t];
    __syncthreads();

    const int wid = t >> 5;
    const int ln  = t & 31;
    const int gi  = ln >> 2;        // fragment row 0..7
    const int tg  = ln & 3;         // fragment col group
    const int mp  = wid >> 2;       // window quad 0..1 (windows 4mp..4mp+3)
    const int cs  = wid & 3;        // chunk quarter
    // attention identity
    const int aw   = wid;           // warp = window
    const int hsel = (t >> 4) & 1;
    const int ti   = t & 15;

    for (int g = blockIdx.x; g < NTILES; g += gridDim.x) {
        // ================= QKV GEMM =================
        {
            // A fragments: 4 windows x 6 ksteps x 4 regs (fp16 pairs)
            u32 af[4][6][4];
            #pragma unroll
            for (int wd = 0; wd < 4; wd++) {
                const float* xr = x + ((size_t)g * 128 + (mp * 4 + wd) * 16 + gi) * 96;
                #pragma unroll
                for (int ks = 0; ks < 6; ks++) {
                    float2 v0 = *(const float2*)(xr + ks * 16 + 2 * tg);
                    float2 v1 = *(const float2*)(xr + 768 + ks * 16 + 2 * tg);
                    float2 v2 = *(const float2*)(xr + ks * 16 + 2 * tg + 8);
                    float2 v3 = *(const float2*)(xr + 768 + ks * 16 + 2 * tg + 8);
                    af[wd][ks][0] = p16(v0.x, v0.y);
                    af[wd][ks][1] = p16(v1.x, v1.y);
                    af[wd][ks][2] = p16(v2.x, v2.y);
                    af[wd][ks][3] = p16(v3.x, v3.y);
                }
            }
            // 9 chunks of 8 output cols each (this warp's quarter of 36)
            #pragma unroll 1
            for (int j = 0; j < 9; j++) {
                const int cq = cs * 9 + j;
                float2 bb = *(const float2*)&BQs[cq * 8 + 2 * tg];
                float c[4][4];
                #pragma unroll
                for (int wd = 0; wd < 4; wd++) {
                    c[wd][0] = bb.x; c[wd][1] = bb.y;
                    c[wd][2] = bb.x; c[wd][3] = bb.y;
                }
                const u32* bp = PQs + (size_t)cq * 384 + ln * 2;
                #pragma unroll
                for (int ks = 0; ks < 6; ks++) {
                    u32 b0 = bp[ks * 64], b1 = bp[ks * 64 + 1];
                    #pragma unroll
                    for (int wd = 0; wd < 4; wd++)
                        mma16(c[wd][0], c[wd][1], c[wd][2], c[wd][3],
                              af[wd][ks][0], af[wd][ks][1], af[wd][ks][2], af[wd][ks][3],
                              b0, b1);
                }
                #pragma unroll
                for (int wd = 0; wd < 4; wd++) {
                    float* qr = &QSf[((mp * 4 + wd) * 16 + gi) * QSTR + cq * 8 + 2 * tg];
                    *(float2*)qr                = make_float2(c[wd][0], c[wd][1]);
                    *(float2*)(qr + 8 * QSTR)   = make_float2(c[wd][2], c[wd][3]);
                }
            }
        }
        __syncthreads();

        // ================= Attention (no internal syncs) =================
        {
            const int arow = aw * 16 + ti;
            float m[16];
            {
                const float4* mpt = (const float4*)(mask +
                    (size_t)((g * 8 + aw) % L_DIM) * 256 + ti * 16);
                float4 m0 = mpt[0], m1 = mpt[1], m2 = mpt[2], m3 = mpt[3];
                m[0]=m0.x; m[1]=m0.y; m[2]=m0.z; m[3]=m0.w;
                m[4]=m1.x; m[5]=m1.y; m[6]=m1.z; m[7]=m1.w;
                m[8]=m2.x; m[9]=m2.y; m[10]=m2.z; m[11]=m2.w;
                m[12]=m3.x; m[13]=m3.y; m[14]=m3.z; m[15]=m3.w;
            }
            #pragma unroll 1
            for (int hp = 0; hp < 4; hp++) {
                const int h = 2 * hp + hsel;
                const float4* qp = (const float4*)&QSf[arow * QSTR + h * 12];
                float4 q0 = qp[0], q1 = qp[1], q2 = qp[2];
                float q[12] = { q0.x*SCALE, q0.y*SCALE, q0.z*SCALE, q0.w*SCALE,
                                q1.x*SCALE, q1.y*SCALE, q1.z*SCALE, q1.w*SCALE,
                                q2.x*SCALE, q2.y*SCALE, q2.z*SCALE, q2.w*SCALE };
                const float* rb = RBG + hp * 512 + ti * 32 + hsel * 16;
                float sc[16];
                #pragma unroll
                for (int j = 0; j < 16; j++) {
                    const float4* kk = (const float4*)&QSf[(aw * 16 + j) * QSTR + 96 + h * 12];
                    float4 k0 = kk[0], k1 = kk[1], k2 = kk[2];
                    float s = __ldg(rb + j) + m[j];
                    s += q[0]*k0.x + q[1]*k0.y + q[2] *k0.z + q[3] *k0.w
                       + q[4]*k1.x + q[5]*k1.y + q[6] *k1.z + q[7] *k1.w
                       + q[8]*k2.x + q[9]*k2.y + q[10]*k2.z + q[11]*k2.w;
                    sc[j] = s;
                }
                float mx = sc[0];
                #pragma unroll
                for (int j = 1; j < 16; j++) mx = fmaxf(mx, sc[j]);
                float sum = 0.f;
                #pragma unroll
                for (int j = 0; j < 16; j++) { sc[j] = __expf(sc[j] - mx); sum += sc[j]; }
                float inv = __fdividef(1.f, sum);

                float o[12];
                #pragma unroll
                for (int d = 0; d < 12; d++) o[d] = 0.f;
                #pragma unroll
                for (int j = 0; j < 16; j++) {
                    const float4* vv = (const float4*)&QSf[(aw * 16 + j) * QSTR + 192 + h * 12];
                    float4 v0 = vv[0], v1 = vv[1], v2 = vv[2];
                    float p = sc[j];
                    o[0] += p*v0.x; o[1] += p*v0.y; o[2]  += p*v0.z; o[3]  += p*v0.w;
                    o[4] += p*v1.x; o[5] += p*v1.y; o[6]  += p*v1.z; o[7]  += p*v1.w;
                    o[8] += p*v2.x; o[9] += p*v2.y; o[10] += p*v2.z; o[11] += p*v2.w;
                }
                // overwrite own Q cells in place (out col == Q col)
                float* op = &QSf[arow * QSTR + h * 12];
                ((float4*)op)[0] = make_float4(o[0]*inv, o[1]*inv, o[2]*inv, o[3]*inv);
                ((float4*)op)[1] = make_float4(o[4]*inv, o[5]*inv, o[6]*inv, o[7]*inv);
                ((float4*)op)[2] = make_float4(o[8]*inv, o[9]*inv, o[10]*inv, o[11]*inv);
            }
        }
        __syncthreads();

        // ================= Proj GEMM =================
        {
            u32 pf[4][6][4];
            #pragma unroll
            for (int wd = 0; wd < 4; wd++) {
                const float* orow = &QSf[((mp * 4 + wd) * 16 + gi) * QSTR];
                #pragma unroll
                for (int ks = 0; ks < 6; ks++) {
                    float2 v0 = *(const float2*)(orow + ks * 16 + 2 * tg);
                    float2 v1 = *(const float2*)(orow + 8 * QSTR + ks * 16 + 2 * tg);
                    float2 v2 = *(const float2*)(orow + ks * 16 + 2 * tg + 8);
                    float2 v3 = *(const float2*)(orow + 8 * QSTR + ks * 16 + 2 * tg + 8);
                    pf[wd][ks][0] = p16(v0.x, v0.y);
                    pf[wd][ks][1] = p16(v1.x, v1.y);
                    pf[wd][ks][2] = p16(v2.x, v2.y);
                    pf[wd][ks][3] = p16(v3.x, v3.y);
                }
            }
            #pragma unroll 1
            for (int j = 0; j < 3; j++) {
                const int cq = cs * 3 + j;
                float2 bb = *(const float2*)&BPs[cq * 8 + 2 * tg];
                float c[4][4];
                #pragma unroll
                for (int wd = 0; wd < 4; wd++) {
                    c[wd][0] = bb.x; c[wd][1] = bb.y;
                    c[wd][2] = bb.x; c[wd][3] = bb.y;
                }
                const u32* bp = PRJs + (size_t)cq * 384 + ln * 2;
                #pragma unroll
                for (int ks = 0; ks < 6; ks++) {
                    u32 b0 = bp[ks * 64], b1 = bp[ks * 64 + 1];
                    #pragma unroll
                    for (int wd = 0; wd < 4; wd++)
                        mma16(c[wd][0], c[wd][1], c[wd][2], c[wd][3],
                              pf[wd][ks][0], pf[wd][ks][1], pf[wd][ks][2], pf[wd][ks][3],
                              b0, b1);
                }
                #pragma unroll
                for (int wd = 0; wd < 4; wd++) {
                    float* og = out + ((size_t)g * 128 + (mp * 4 + wd) * 16 + gi) * 96
                                    + cq * 8 + 2 * tg;
                    *(float2*)og              = make_float2(c[wd][0], c[wd][1]);
                    *(float2*)(og + 8 * 96)   = make_float2(c[wd][2], c[wd][3]);
                }
            }
        }
        __syncthreads();   // QS reuse by next tile's GEMM
    }
}

extern "C" void kernel_launch(void* const* d_in, const int* in_sizes, int n_in,
                              void* d_out, int out_size)
{
    const float* x          = (const float*)d_in[0];
    const float* mask       = (const float*)d_in[1];
    const float* qkv_w      = (const float*)d_in[2];
    const float* qkv_b      = (const float*)d_in[3];
    const float* proj_w     = (const float*)d_in[4];
    const float* proj_b     = (const float*)d_in[5];
    const float* bias_table = (const float*)d_in[6];
    float* out = (float*)d_out;

    int sms = 148;
    cudaDeviceGetAttribute(&sms, cudaDevAttrMultiProcessorCount, 0);
    cudaFuncSetAttribute(win_attn_kernel,
                         cudaFuncAttributeMaxDynamicSharedMemorySize, SMEM_BYTES);

    win_attn_kernel<<<sms, 256, SMEM_BYTES>>>(x, mask, qkv_w, qkv_b,
                                              proj_w, proj_b, bias_table, out);
}

// round 8
// speedup vs baseline: 1.0024x; 1.0005x over previous
#include <cuda_runtime.h>
#include <cuda_fp16.h>

// WindowAttention: fp16 m16n8k16 mma GEMMs + fp32 attention, fused buffers.
// 50176 windows of [16 tok, 96 ch], H=8, D=12. Persistent CTAs, 8 warps.
// Per tile: 8 windows. GEMM warps = (window-quad mp, chunk-quarter cs).
// QS[128][292]: cols 0-95 Q (overwritten in place by attn-out), 96-191 K, 192-287 V.

#define NWIN   50176
#define NTILES (NWIN / 8)      // 6272
#define L_DIM  3136
#define SCALE  0.28867513459481287f
#define QSTR   292             // QS row stride (floats)

// SMEM layout (bytes)
#define OFF_PQ   0             // QKV B-pack fp16: 36cq*6ks*32ln*2u32 = 55296
#define OFF_QS   55296         // [128][292] f32 = 149504
#define OFF_PRJ  204800        // proj B-pack fp16: 12*6*64 u32 = 18432
#define OFF_BQ   223232        // qkv_bias 288 f
#define OFF_BP   224384        // proj_bias 96 f
#define SMEM_BYTES 224768

typedef unsigned int u32;

__device__ float RBG[4 * 16 * 2 * 16];   // rel-bias [hp][ti][hsel][j], L1-cached

__device__ __forceinline__ u32 p16(float a, float b) {
    __half2 h = __floats2half2_rn(a, b);
    return *(u32*)&h;
}
__device__ __forceinline__ void mma16(float& c0, float& c1, float& c2, float& c3,
                                      u32 a0, u32 a1, u32 a2, u32 a3,
                                      u32 b0, u32 b1) {
    asm volatile(
        "mma.sync.aligned.m16n8k16.row.col.f32.f16.f16.f32 "
        "{%0,%1,%2,%3}, {%4,%5,%6,%7}, {%8,%9}, {%0,%1,%2,%3};"
        : "+f"(c0), "+f"(c1), "+f"(c2), "+f"(c3)
        : "r"(a0), "r"(a1), "r"(a2), "r"(a3), "r"(b0), "r"(b1));
}

__global__ __launch_bounds__(256, 1)
void win_attn_kernel(const float* __restrict__ x,
                     const float* __restrict__ mask,
                     const float* __restrict__ qkv_w,
                     const float* __restrict__ qkv_b,
                     const float* __restrict__ proj_w,
                     const float* __restrict__ proj_b,
                     const float* __restrict__ bias_table,
                     float* __restrict__ out)
{
    extern __shared__ char smb[];
    u32*   PQs  = (u32*)(smb + OFF_PQ);
    float* QSf  = (float*)(smb + OFF_QS);
    u32*   PRJs = (u32*)(smb + OFF_PRJ);
    float* BQs  = (float*)(smb + OFF_BQ);
    float* BPs  = (float*)(smb + OFF_BP);

    const int t = threadIdx.x;

    // ---- One-time staging ----
    // QKV B-pack: b0={W[k0][n],W[k0+1][n]}, b1={W[k0+8][n],W[k0+9][n]} fp16
    for (int i = t; i < 36 * 6 * 32; i += 256) {
        int cq = i / 192, r = i % 192, ks = r / 32, lnn = r % 32;
        int gi = lnn >> 2, tg = lnn & 3;
        int k0 = ks * 16 + 2 * tg, n = cq * 8 + gi;
        PQs[i * 2 + 0] = p16(qkv_w[k0 * 288 + n],       qkv_w[(k0 + 1) * 288 + n]);
        PQs[i * 2 + 1] = p16(qkv_w[(k0 + 8) * 288 + n], qkv_w[(k0 + 9) * 288 + n]);
    }
    // proj B-pack
    for (int i = t; i < 12 * 6 * 32; i += 256) {
        int cq = i / 192, r = i % 192, ks = r / 32, lnn = r % 32;
        int gi = lnn >> 2, tg = lnn & 3;
        int k0 = ks * 16 + 2 * tg, n = cq * 8 + gi;
        PRJs[i * 2 + 0] = p16(proj_w[k0 * 96 + n],       proj_w[(k0 + 1) * 96 + n]);
        PRJs[i * 2 + 1] = p16(proj_w[(k0 + 8) * 96 + n], proj_w[(k0 + 9) * 96 + n]);
    }
    // rel-bias expanded table -> global (all CTAs write identical values)
    for (int i = t; i < 2048; i += 256) {
        int hp = i >> 9, ti = (i >> 5) & 15, hsel = (i >> 4) & 1, j = i & 15;
        int h  = 2 * hp + hsel;
        int d0 = (ti & 3)  - (j & 3)  + 3;
        int d1 = (ti >> 2) - (j >> 2) + 3;
        RBG[i] = bias_table[(d0 * 7 + d1) * 8 + h];
    }
    for (int i = t; i < 288; i += 256) BQs[i] = qkv_b[i];
    if (t < 96) BPs[t] = proj_b[t];
    __syncthreads();

    const int wid = t >> 5;
    const int ln  = t & 31;
    const int gi  = ln >> 2;        // fragment row 0..7
    const int tg  = ln & 3;         // fragment col group
    const int mp  = wid >> 2;       // window quad 0..1 (windows 4mp..4mp+3)
    const int cs  = wid & 3;        // chunk quarter
    // attention identity
    const int aw   = wid;           // warp = window
    const int hsel = (t >> 4) & 1;
    const int ti   = t & 15;

    for (int g = blockIdx.x; g < NTILES; g += gridDim.x) {
        // ================= QKV GEMM =================
        {
            // A fragments: 4 windows x 6 ksteps x 4 regs (fp16 pairs)
            u32 af[4][6][4];
            #pragma unroll
            for (int wd = 0; wd < 4; wd++) {
                const float* xr = x + ((size_t)g * 128 + (mp * 4 + wd) * 16 + gi) * 96;
                #pragma unroll
                for (int ks = 0; ks < 6; ks++) {
                    float2 v0 = *(const float2*)(xr + ks * 16 + 2 * tg);
                    float2 v1 = *(const float2*)(xr + 768 + ks * 16 + 2 * tg);
                    float2 v2 = *(const float2*)(xr + ks * 16 + 2 * tg + 8);
                    float2 v3 = *(const float2*)(xr + 768 + ks * 16 + 2 * tg + 8);
                    af[wd][ks][0] = p16(v0.x, v0.y);
                    af[wd][ks][1] = p16(v1.x, v1.y);
                    af[wd][ks][2] = p16(v2.x, v2.y);
                    af[wd][ks][3] = p16(v3.x, v3.y);
                }
            }
            // 9 chunks of 8 output cols each (this warp's quarter of 36)
            #pragma unroll 1
            for (int j = 0; j < 9; j++) {
                const int cq = cs * 9 + j;
                float2 bb = *(const float2*)&BQs[cq * 8 + 2 * tg];
                float c[4][4];
                #pragma unroll
                for (int wd = 0; wd < 4; wd++) {
                    c[wd][0] = bb.x; c[wd][1] = bb.y;
                    c[wd][2] = bb.x; c[wd][3] = bb.y;
                }
                const u32* bp = PQs + (size_t)cq * 384 + ln * 2;
                #pragma unroll
                for (int ks = 0; ks < 6; ks++) {
                    u32 b0 = bp[ks * 64], b1 = bp[ks * 64 + 1];
                    #pragma unroll
                    for (int wd = 0; wd < 4; wd++)
                        mma16(c[wd][0], c[wd][1], c[wd][2], c[wd][3],
                              af[wd][ks][0], af[wd][ks][1], af[wd][ks][2], af[wd][ks][3],
                              b0, b1);
                }
                #pragma unroll
                for (int wd = 0; wd < 4; wd++) {
                    float* qr = &QSf[((mp * 4 + wd) * 16 + gi) * QSTR + cq * 8 + 2 * tg];
                    *(float2*)qr                = make_float2(c[wd][0], c[wd][1]);
                    *(float2*)(qr + 8 * QSTR)   = make_float2(c[wd][2], c[wd][3]);
                }
            }
        }
        __syncthreads();

        // ================= Attention (no internal syncs) =================
        {
            const int arow = aw * 16 + ti;
            float m[16];
            {
                const float4* mpt = (const float4*)(mask +
                    (size_t)((g * 8 + aw) % L_DIM) * 256 + ti * 16);
                float4 m0 = mpt[0], m1 = mpt[1], m2 = mpt[2], m3 = mpt[3];
                m[0]=m0.x; m[1]=m0.y; m[2]=m0.z; m[3]=m0.w;
                m[4]=m1.x; m[5]=m1.y; m[6]=m1.z; m[7]=m1.w;
                m[8]=m2.x; m[9]=m2.y; m[10]=m2.z; m[11]=m2.w;
                m[12]=m3.x; m[13]=m3.y; m[14]=m3.z; m[15]=m3.w;
            }
            #pragma unroll 1
            for (int hp = 0; hp < 4; hp++) {
                const int h = 2 * hp + hsel;
                const float4* qp = (const float4*)&QSf[arow * QSTR + h * 12];
                float4 q0 = qp[0], q1 = qp[1], q2 = qp[2];
                float q[12] = { q0.x*SCALE, q0.y*SCALE, q0.z*SCALE, q0.w*SCALE,
                                q1.x*SCALE, q1.y*SCALE, q1.z*SCALE, q1.w*SCALE,
                                q2.x*SCALE, q2.y*SCALE, q2.z*SCALE, q2.w*SCALE };
                const float* rb = RBG + hp * 512 + ti * 32 + hsel * 16;
                float sc[16];
                #pragma unroll
                for (int j = 0; j < 16; j++) {
                    const float4* kk = (const float4*)&QSf[(aw * 16 + j) * QSTR + 96 + h * 12];
                    float4 k0 = kk[0], k1 = kk[1], k2 = kk[2];
                    float s = __ldg(rb + j) + m[j];
                    s += q[0]*k0.x + q[1]*k0.y + q[2] *k0.z + q[3] *k0.w
                       + q[4]*k1.x + q[5]*k1.y + q[6] *k1.z + q[7] *k1.w
                       + q[8]*k2.x + q[9]*k2.y + q[10]*k2.z + q[11]*k2.w;
                    sc[j] = s;
                }
                float mx = sc[0];
                #pragma unroll
                for (int j = 1; j < 16; j++) mx = fmaxf(mx, sc[j]);
                float sum = 0.f;
                #pragma unroll
                for (int j = 0; j < 16; j++) { sc[j] = __expf(sc[j] - mx); sum += sc[j]; }
                float inv = __fdividef(1.f, sum);

                float o[12];
                #pragma unroll
                for (int d = 0; d < 12; d++) o[d] = 0.f;
                #pragma unroll
                for (int j = 0; j < 16; j++) {
                    const float4* vv = (const float4*)&QSf[(aw * 16 + j) * QSTR + 192 + h * 12];
                    float4 v0 = vv[0], v1 = vv[1], v2 = vv[2];
                    float p = sc[j];
                    o[0] += p*v0.x; o[1] += p*v0.y; o[2]  += p*v0.z; o[3]  += p*v0.w;
                    o[4] += p*v1.x; o[5] += p*v1.y; o[6]  += p*v1.z; o[7]  += p*v1.w;
                    o[8] += p*v2.x; o[9] += p*v2.y; o[10] += p*v2.z; o[11] += p*v2.w;
                }
                // overwrite own Q cells in place (out col == Q col)
                float* op = &QSf[arow * QSTR + h * 12];
                ((float4*)op)[0] = make_float4(o[0]*inv, o[1]*inv, o[2]*inv, o[3]*inv);
                ((float4*)op)[1] = make_float4(o[4]*inv, o[5]*inv, o[6]*inv, o[7]*inv);
                ((float4*)op)[2] = make_float4(o[8]*inv, o[9]*inv, o[10]*inv, o[11]*inv);
            }
        }
        __syncthreads();

        // ================= Proj GEMM =================
        {
            u32 pf[4][6][4];
            #pragma unroll
            for (int wd = 0; wd < 4; wd++) {
                const float* orow = &QSf[((mp * 4 + wd) * 16 + gi) * QSTR];
                #pragma unroll
                for (int ks = 0; ks < 6; ks++) {
                    float2 v0 = *(const float2*)(orow + ks * 16 + 2 * tg);
                    float2 v1 = *(const float2*)(orow + 8 * QSTR + ks * 16 + 2 * tg);
                    float2 v2 = *(const float2*)(orow + ks * 16 + 2 * tg + 8);
                    float2 v3 = *(const float2*)(orow + 8 * QSTR + ks * 16 + 2 * tg + 8);
                    pf[wd][ks][0] = p16(v0.x, v0.y);
                    pf[wd][ks][1] = p16(v1.x, v1.y);
                    pf[wd][ks][2] = p16(v2.x, v2.y);
                    pf[wd][ks][3] = p16(v3.x, v3.y);
                }
            }
            #pragma unroll 1
            for (int j = 0; j < 3; j++) {
                const int cq = cs * 3 + j;
                float2 bb = *(const float2*)&BPs[cq * 8 + 2 * tg];
                float c[4][4];
                #pragma unroll
                for (int wd = 0; wd < 4; wd++) {
                    c[wd][0] = bb.x; c[wd][1] = bb.y;
                    c[wd][2] = bb.x; c[wd][3] = bb.y;
                }
                const u32* bp = PRJs + (size_t)cq * 384 + ln * 2;
                #pragma unroll
                for (int ks = 0; ks < 6; ks++) {
                    u32 b0 = bp[ks * 64], b1 = bp[ks * 64 + 1];
                    #pragma unroll
                    for (int wd = 0; wd < 4; wd++)
                        mma16(c[wd][0], c[wd][1], c[wd][2], c[wd][3],
                              pf[wd][ks][0], pf[wd][ks][1], pf[wd][ks][2], pf[wd][ks][3],
                              b0, b1);
                }
                #pragma unroll
                for (int wd = 0; wd < 4; wd++) {
                    float* og = out + ((size_t)g * 128 + (mp * 4 + wd) * 16 + gi) * 96
                                    + cq * 8 + 2 * tg;
                    *(float2*)og              = make_float2(c[wd][0], c[wd][1]);
                    *(float2*)(og + 8 * 96)   = make_float2(c[wd][2], c[wd][3]);
                }
            }
        }
        __syncthreads();   // QS reuse by next tile's GEMM
    }
}

extern "C" void kernel_launch(void* const* d_in, const int* in_sizes, int n_in,
                              void* d_out, int out_size)
{
    const float* x          = (const float*)d_in[0];
    const float* mask       = (const float*)d_in[1];
    const float* qkv_w      = (const float*)d_in[2];
    const float* qkv_b      = (const float*)d_in[3];
    const float* proj_w     = (const float*)d_in[4];
    const float* proj_b     = (const float*)d_in[5];
    const float* bias_table = (const float*)d_in[6];
    float* out = (float*)d_out;

    int sms = 148;
    cudaDeviceGetAttribute(&sms, cudaDevAttrMultiProcessorCount, 0);
    cudaFuncSetAttribute(win_attn_kernel,
                         cudaFuncAttributeMaxDynamicSharedMemorySize, SMEM_BYTES);

    win_attn_kernel<<<sms, 256, SMEM_BYTES>>>(x, mask, qkv_w, qkv_b,
                                              proj_w, proj_b, bias_table, out);
}

// round 9
// speedup vs baseline: 1.1501x; 1.1473x over previous
#include <cuda_runtime.h>
#include <cuda_fp16.h>

// WindowAttention: fp16 m16n8k16 mma GEMMs + fp32 attention.
// QS tile in fp16 SMEM; B-packs in L1-cached global; 2 CTAs/SM.
// 50176 windows of [16 tok, 96 ch], H=8, D=12. 8 warps/CTA, tile = 8 windows.

#define NWIN   50176
#define NTILES (NWIN / 8)      // 6272
#define L_DIM  3136
#define SCALE  0.28867513459481287f
#define QSTR   292             // QS row stride in halfs (146 words, ti*18 mod 32 distinct)

// SMEM layout (bytes)
#define OFF_QS   0             // half [128][292] = 74752
#define OFF_BQ   74752         // qkv_bias 288 f32
#define OFF_BP   75904         // proj_bias 96 f32
#define SMEM_BYTES 76288

typedef unsigned int u32;

__device__ u32   PQG[36 * 6 * 64];    // QKV B-pack (fp16 pairs)
__device__ u32   PRJG[12 * 6 * 64];   // proj B-pack
__device__ float RBG[4 * 16 * 2 * 16];// rel-bias [hp][ti][hsel][j]

__device__ __forceinline__ u32 p16(float a, float b) {
    __half2 h = __floats2half2_rn(a, b);
    return *(u32*)&h;
}
__device__ __forceinline__ void mma16(float& c0, float& c1, float& c2, float& c3,
                                      u32 a0, u32 a1, u32 a2, u32 a3,
                                      u32 b0, u32 b1) {
    asm volatile(
        "mma.sync.aligned.m16n8k16.row.col.f32.f16.f16.f32 "
        "{%0,%1,%2,%3}, {%4,%5,%6,%7}, {%8,%9}, {%0,%1,%2,%3};"
        : "+f"(c0), "+f"(c1), "+f"(c2), "+f"(c3)
        : "r"(a0), "r"(a1), "r"(a2), "r"(a3), "r"(b0), "r"(b1));
}
// load 4 halfs (8B) from SMEM -> 4 floats
__device__ __forceinline__ void ld_h4(const __half* p, float* f) {
    uint2 u = *(const uint2*)p;
    float2 a = __half22float2(*(__half2*)&u.x);
    float2 b = __half22float2(*(__half2*)&u.y);
    f[0] = a.x; f[1] = a.y; f[2] = b.x; f[3] = b.y;
}

__global__ __launch_bounds__(256, 2)
void win_attn_kernel(const float* __restrict__ x,
                     const float* __restrict__ mask,
                     const float* __restrict__ qkv_w,
                     const float* __restrict__ qkv_b,
                     const float* __restrict__ proj_w,
                     const float* __restrict__ proj_b,
                     const float* __restrict__ bias_table,
                     float* __restrict__ out)
{
    extern __shared__ char smb[];
    __half* QSh = (__half*)(smb + OFF_QS);
    float*  BQs = (float*)(smb + OFF_BQ);
    float*  BPs = (float*)(smb + OFF_BP);

    const int t = threadIdx.x;

    // ---- One-time staging (global packs written identically by all CTAs) ----
    for (int i = t; i < 36 * 6 * 32; i += 256) {
        int cq = i / 192, r = i % 192, ks = r / 32, lnn = r % 32;
        int gi = lnn >> 2, tg = lnn & 3;
        int k0 = ks * 16 + 2 * tg, n = cq * 8 + gi;
        PQG[i * 2 + 0] = p16(qkv_w[k0 * 288 + n],       qkv_w[(k0 + 1) * 288 + n]);
        PQG[i * 2 + 1] = p16(qkv_w[(k0 + 8) * 288 + n], qkv_w[(k0 + 9) * 288 + n]);
    }
    for (int i = t; i < 12 * 6 * 32; i += 256) {
        int cq = i / 192, r = i % 192, ks = r / 32, lnn = r % 32;
        int gi = lnn >> 2, tg = lnn & 3;
        int k0 = ks * 16 + 2 * tg, n = cq * 8 + gi;
        PRJG[i * 2 + 0] = p16(proj_w[k0 * 96 + n],       proj_w[(k0 + 1) * 96 + n]);
        PRJG[i * 2 + 1] = p16(proj_w[(k0 + 8) * 96 + n], proj_w[(k0 + 9) * 96 + n]);
    }
    for (int i = t; i < 2048; i += 256) {
        int hp = i >> 9, ti = (i >> 5) & 15, hsel = (i >> 4) & 1, j = i & 15;
        int h  = 2 * hp + hsel;
        int d0 = (ti & 3)  - (j & 3)  + 3;
        int d1 = (ti >> 2) - (j >> 2) + 3;
        RBG[i] = bias_table[(d0 * 7 + d1) * 8 + h];
    }
    for (int i = t; i < 288; i += 256) BQs[i] = qkv_b[i];
    if (t < 96) BPs[t] = proj_b[t];
    __syncthreads();

    const int wid = t >> 5;
    const int ln  = t & 31;
    const int gi  = ln >> 2;        // fragment row 0..7
    const int tg  = ln & 3;         // fragment col group
    const int wp  = wid >> 1;       // window pair 0..3 (windows 2wp, 2wp+1)
    const int cs  = wid & 1;        // chunk half
    // attention identity
    const int aw   = wid;           // warp = window
    const int hsel = (t >> 4) & 1;
    const int ti   = t & 15;

    for (int g = blockIdx.x; g < NTILES; g += gridDim.x) {
        // ================= QKV GEMM =================
        {
            u32 af[2][6][4];
            #pragma unroll
            for (int wd = 0; wd < 2; wd++) {
                const float* xr = x + ((size_t)g * 128 + (wp * 2 + wd) * 16 + gi) * 96;
                #pragma unroll
                for (int ks = 0; ks < 6; ks++) {
                    float2 v0 = *(const float2*)(xr + ks * 16 + 2 * tg);
                    float2 v1 = *(const float2*)(xr + 768 + ks * 16 + 2 * tg);
                    float2 v2 = *(const float2*)(xr + ks * 16 + 2 * tg + 8);
                    float2 v3 = *(const float2*)(xr + 768 + ks * 16 + 2 * tg + 8);
                    af[wd][ks][0] = p16(v0.x, v0.y);
                    af[wd][ks][1] = p16(v1.x, v1.y);
                    af[wd][ks][2] = p16(v2.x, v2.y);
                    af[wd][ks][3] = p16(v3.x, v3.y);
                }
            }
            #pragma unroll 1
            for (int j = 0; j < 18; j++) {
                const int cq = cs * 18 + j;
                float2 bb = *(const float2*)&BQs[cq * 8 + 2 * tg];
                float c[2][4];
                c[0][0] = bb.x; c[0][1] = bb.y; c[0][2] = bb.x; c[0][3] = bb.y;
                c[1][0] = bb.x; c[1][1] = bb.y; c[1][2] = bb.x; c[1][3] = bb.y;
                const u32* bp = PQG + (size_t)cq * 384 + ln * 2;
                #pragma unroll
                for (int ks = 0; ks < 6; ks++) {
                    uint2 bv = __ldg((const uint2*)(bp + ks * 64));
                    mma16(c[0][0], c[0][1], c[0][2], c[0][3],
                          af[0][ks][0], af[0][ks][1], af[0][ks][2], af[0][ks][3],
                          bv.x, bv.y);
                    mma16(c[1][0], c[1][1], c[1][2], c[1][3],
                          af[1][ks][0], af[1][ks][1], af[1][ks][2], af[1][ks][3],
                          bv.x, bv.y);
                }
                #pragma unroll
                for (int wd = 0; wd < 2; wd++) {
                    __half* qr = &QSh[((wp * 2 + wd) * 16 + gi) * QSTR + cq * 8 + 2 * tg];
                    *(u32*)qr              = p16(c[wd][0], c[wd][1]);
                    *(u32*)(qr + 8 * QSTR) = p16(c[wd][2], c[wd][3]);
                }
            }
        }
        __syncthreads();

        // ================= Attention (fp32 math, fp16 operands) =================
        {
            const int arow = aw * 16 + ti;
            float m[16];
            {
                const float4* mpt = (const float4*)(mask +
                    (size_t)((g * 8 + aw) % L_DIM) * 256 + ti * 16);
                float4 m0 = mpt[0], m1 = mpt[1], m2 = mpt[2], m3 = mpt[3];
                m[0]=m0.x; m[1]=m0.y; m[2]=m0.z; m[3]=m0.w;
                m[4]=m1.x; m[5]=m1.y; m[6]=m1.z; m[7]=m1.w;
                m[8]=m2.x; m[9]=m2.y; m[10]=m2.z; m[11]=m2.w;
                m[12]=m3.x; m[13]=m3.y; m[14]=m3.z; m[15]=m3.w;
            }
            #pragma unroll 1
            for (int hp = 0; hp < 4; hp++) {
                const int h = 2 * hp + hsel;
                float q[12];
                {
                    const __half* qp = &QSh[arow * QSTR + h * 12];
                    ld_h4(qp, q); ld_h4(qp + 4, q + 4); ld_h4(qp + 8, q + 8);
                    #pragma unroll
                    for (int d = 0; d < 12; d++) q[d] *= SCALE;
                }
                const float* rb = RBG + hp * 512 + ti * 32 + hsel * 16;
                float sc[16];
                #pragma unroll
                for (int j = 0; j < 16; j++) {
                    float kf[12];
                    const __half* kp = &QSh[(aw * 16 + j) * QSTR + 96 + h * 12];
                    ld_h4(kp, kf); ld_h4(kp + 4, kf + 4); ld_h4(kp + 8, kf + 8);
                    float s = __ldg(rb + j) + m[j];
                    #pragma unroll
                    for (int d = 0; d < 12; d++) s += q[d] * kf[d];
                    sc[j] = s;
                }
                float mx = sc[0];
                #pragma unroll
                for (int j = 1; j < 16; j++) mx = fmaxf(mx, sc[j]);
                float sum = 0.f;
                #pragma unroll
                for (int j = 0; j < 16; j++) { sc[j] = __expf(sc[j] - mx); sum += sc[j]; }
                float inv = __fdividef(1.f, sum);

                float o[12];
                #pragma unroll
                for (int d = 0; d < 12; d++) o[d] = 0.f;
                #pragma unroll
                for (int j = 0; j < 16; j++) {
                    float vf[12];
                    const __half* vp = &QSh[(aw * 16 + j) * QSTR + 192 + h * 12];
                    ld_h4(vp, vf); ld_h4(vp + 4, vf + 4); ld_h4(vp + 8, vf + 8);
                    float p = sc[j];
                    #pragma unroll
                    for (int d = 0; d < 12; d++) o[d] += p * vf[d];
                }
                // overwrite own Q cells in place (out col == Q col), fp16
                __half* op = &QSh[arow * QSTR + h * 12];
                uint2 s0, s1;
                s0.x = p16(o[0]*inv,  o[1]*inv);  s0.y = p16(o[2]*inv,  o[3]*inv);
                s1.x = p16(o[4]*inv,  o[5]*inv);  s1.y = p16(o[6]*inv,  o[7]*inv);
                *(uint2*)op       = s0;
                *(uint2*)(op + 4) = s1;
                *(u32*)(op + 8)   = p16(o[8]*inv,  o[9]*inv);
                *(u32*)(op + 10)  = p16(o[10]*inv, o[11]*inv);
            }
        }
        __syncthreads();

        // ================= Proj GEMM (A-frags read directly as fp16) ==========
        {
            u32 pf[2][6][4];
            #pragma unroll
            for (int wd = 0; wd < 2; wd++) {
                const __half* orow = &QSh[((wp * 2 + wd) * 16 + gi) * QSTR];
                #pragma unroll
                for (int ks = 0; ks < 6; ks++) {
                    pf[wd][ks][0] = *(const u32*)(orow + ks * 16 + 2 * tg);
                    pf[wd][ks][1] = *(const u32*)(orow + 8 * QSTR + ks * 16 + 2 * tg);
                    pf[wd][ks][2] = *(const u32*)(orow + ks * 16 + 2 * tg + 8);
                    pf[wd][ks][3] = *(const u32*)(orow + 8 * QSTR + ks * 16 + 2 * tg + 8);
                }
            }
            #pragma unroll 1
            for (int j = 0; j < 6; j++) {
                const int cq = cs * 6 + j;
                float2 bb = *(const float2*)&BPs[cq * 8 + 2 * tg];
                float c[2][4];
                c[0][0] = bb.x; c[0][1] = bb.y; c[0][2] = bb.x; c[0][3] = bb.y;
                c[1][0] = bb.x; c[1][1] = bb.y; c[1][2] = bb.x; c[1][3] = bb.y;
                const u32* bp = PRJG + (size_t)cq * 384 + ln * 2;
                #pragma unroll
                for (int ks = 0; ks < 6; ks++) {
                    uint2 bv = __ldg((const uint2*)(bp + ks * 64));
                    mma16(c[0][0], c[0][1], c[0][2], c[0][3],
                          pf[0][ks][0], pf[0][ks][1], pf[0][ks][2], pf[0][ks][3],
                          bv.x, bv.y);
                    mma16(c[1][0], c[1][1], c[1][2], c[1][3],
                          pf[1][ks][0], pf[1][ks][1], pf[1][ks][2], pf[1][ks][3],
                          bv.x, bv.y);
                }
                #pragma unroll
                for (int wd = 0; wd < 2; wd++) {
                    float* og = out + ((size_t)g * 128 + (wp * 2 + wd) * 16 + gi) * 96
                                    + cq * 8 + 2 * tg;
                    *(float2*)og            = make_float2(c[wd][0], c[wd][1]);
                    *(float2*)(og + 8 * 96) = make_float2(c[wd][2], c[wd][3]);
                }
            }
        }
        __syncthreads();   // QS reuse by next tile's GEMM
    }
}

extern "C" void kernel_launch(void* const* d_in, const int* in_sizes, int n_in,
                              void* d_out, int out_size)
{
    const float* x          = (const float*)d_in[0];
    const float* mask       = (const float*)d_in[1];
    const float* qkv_w      = (const float*)d_in[2];
    const float* qkv_b      = (const float*)d_in[3];
    const float* proj_w     = (const float*)d_in[4];
    const float* proj_b     = (const float*)d_in[5];
    const float* bias_table = (const float*)d_in[6];
    float* out = (float*)d_out;

    int sms = 148;
    cudaDeviceGetAttribute(&sms, cudaDevAttrMultiProcessorCount, 0);
    cudaFuncSetAttribute(win_attn_kernel,
                         cudaFuncAttributeMaxDynamicSharedMemorySize, SMEM_BYTES);

    win_attn_kernel<<<2 * sms, 256, SMEM_BYTES>>>(x, mask, qkv_w, qkv_b,
                                                  proj_w, proj_b, bias_table, out);
}

// round 10
// speedup vs baseline: 1.7220x; 1.4973x over previous
#include <cuda_runtime.h>
#include <cuda_fp16.h>

// WindowAttention: fully tensor-core pipeline (fp16 m16n8k16), fragment-native SMEM.
// 50176 windows of [16 tok, 96 ch], H=8, D=12. 8 warps/CTA, 2 CTAs/SM, tile = 8 windows.
// QF per window (3072 u32): [h][6 full regs][32] then +1536: [h][6 partial regs][32].
//   full:  Qa0,Qa1, K(c0)b0, K(c1)b0, V(c0)b0, V(c0)b1
//   part:  Qa2,Qa3, K(c0)b1, K(c1)b1, V(c1)b0, V(c1)b1   (pad halves stay zero)
// AF (attn-out, proj-A frags) aliases first 768 u32 of each window block.

#define NWIN   50176
#define NTILES (NWIN / 8)      // 6272
#define L_DIM  3136
#define SCALE  0.28867513459481287f

#define QF_U32   24576         // 8 windows * 3072
#define OFF_BQ   (QF_U32 * 4)          // 98304: qkv_bias 288 f32
#define OFF_BP   (OFF_BQ + 1152)       // proj_bias 96 f32
#define SMEM_BYTES (OFF_BP + 384)      // 99840

typedef unsigned int u32;

__device__ u32   PQG[36 * 6 * 64];     // QKV B-pack (fp16 pairs)
__device__ u32   PRJG[12 * 6 * 64];    // proj B-pack
__device__ float RBG[8 * 16 * 16];     // rel-bias [h][i][j]

__device__ __forceinline__ u32 p16(float a, float b) {
    __half2 h = __floats2half2_rn(a, b);
    return *(u32*)&h;
}
__device__ __forceinline__ void mma16(float& c0, float& c1, float& c2, float& c3,
                                      u32 a0, u32 a1, u32 a2, u32 a3,
                                      u32 b0, u32 b1) {
    asm volatile(
        "mma.sync.aligned.m16n8k16.row.col.f32.f16.f16.f32 "
        "{%0,%1,%2,%3}, {%4,%5,%6,%7}, {%8,%9}, {%0,%1,%2,%3};"
        : "+f"(c0), "+f"(c1), "+f"(c2), "+f"(c3)
        : "r"(a0), "r"(a1), "r"(a2), "r"(a3), "r"(b0), "r"(b1));
}

// Store one C pair (row r = rlow+8*rhalf, cols col,col+1) into fragment slots.
__device__ __forceinline__ void qkv_store_pair(u32* QF, int wb, int sec, int h, int d,
                                               int rlow, int rhalf, float v0, float v1)
{
    int dhi = (d >= 8);
    int base = wb + (dhi ? 1536 : 0) + h * 192;
    if (sec < 2) {
        int f = (sec == 0 ? rhalf : 2 + rhalf);
        QF[base + f * 32 + rlow * 4 + ((d & 7) >> 1)] = p16(v0, v1);
    } else {
        int f = 4 + rhalf;
        __half* H = (__half*)(QF + base + f * 32);
        int tgt = rlow >> 1, hf = rlow & 1;
        H[((d & 7) * 4 + tgt) * 2 + hf]       = __float2half_rn(v0);
        H[(((d + 1) & 7) * 4 + tgt) * 2 + hf] = __float2half_rn(v1);
    }
}

__global__ __launch_bounds__(256, 2)
void win_attn_kernel(const float* __restrict__ x,
                     const float* __restrict__ mask,
                     const float* __restrict__ qkv_w,
                     const float* __restrict__ qkv_b,
                     const float* __restrict__ proj_w,
                     const float* __restrict__ proj_b,
                     const float* __restrict__ bias_table,
                     float* __restrict__ out)
{
    extern __shared__ char smb[];
    u32*   QF  = (u32*)smb;
    float* BQs = (float*)(smb + OFF_BQ);
    float* BPs = (float*)(smb + OFF_BP);

    const int t = threadIdx.x;

    // ---- One-time staging ----
    for (int i = t; i < QF_U32; i += 256) QF[i] = 0;   // pad slots must be zero
    for (int i = t; i < 36 * 6 * 32; i += 256) {
        int cq = i / 192, r = i % 192, ks = r / 32, lnn = r % 32;
        int gg = lnn >> 2, tt = lnn & 3;
        int k0 = ks * 16 + 2 * tt, n = cq * 8 + gg;
        PQG[i * 2 + 0] = p16(qkv_w[k0 * 288 + n],       qkv_w[(k0 + 1) * 288 + n]);
        PQG[i * 2 + 1] = p16(qkv_w[(k0 + 8) * 288 + n], qkv_w[(k0 + 9) * 288 + n]);
    }
    for (int i = t; i < 12 * 6 * 32; i += 256) {
        int cq = i / 192, r = i % 192, ks = r / 32, lnn = r % 32;
        int gg = lnn >> 2, tt = lnn & 3;
        int k0 = ks * 16 + 2 * tt, n = cq * 8 + gg;
        PRJG[i * 2 + 0] = p16(proj_w[k0 * 96 + n],       proj_w[(k0 + 1) * 96 + n]);
        PRJG[i * 2 + 1] = p16(proj_w[(k0 + 8) * 96 + n], proj_w[(k0 + 9) * 96 + n]);
    }
    for (int i = t; i < 2048; i += 256) {
        int h = i >> 8, ii = (i >> 4) & 15, jj = i & 15;
        int d0 = (ii & 3)  - (jj & 3)  + 3;
        int d1 = (ii >> 2) - (jj >> 2) + 3;
        RBG[i] = bias_table[(d0 * 7 + d1) * 8 + h];
    }
    for (int i = t; i < 288; i += 256) BQs[i] = qkv_b[i];
    if (t < 96) BPs[t] = proj_b[t];
    __syncthreads();

    const int wid = t >> 5;
    const int ln  = t & 31;
    const int gi  = ln >> 2;
    const int tg  = ln & 3;
    const int wp  = wid >> 1;       // window pair for GEMM phases
    const int cs  = wid & 1;        // chunk half

    for (int g = blockIdx.x; g < NTILES; g += gridDim.x) {
        // ================= QKV GEMM -> fragment slots =================
        {
            u32 af[2][6][4];
            #pragma unroll
            for (int wd = 0; wd < 2; wd++) {
                const float* xr = x + ((size_t)g * 128 + (wp * 2 + wd) * 16 + gi) * 96;
                #pragma unroll
                for (int ks = 0; ks < 6; ks++) {
                    float2 v0 = *(const float2*)(xr + ks * 16 + 2 * tg);
                    float2 v1 = *(const float2*)(xr + 768 + ks * 16 + 2 * tg);
                    float2 v2 = *(const float2*)(xr + ks * 16 + 2 * tg + 8);
                    float2 v3 = *(const float2*)(xr + 768 + ks * 16 + 2 * tg + 8);
                    af[wd][ks][0] = p16(v0.x, v0.y);
                    af[wd][ks][1] = p16(v1.x, v1.y);
                    af[wd][ks][2] = p16(v2.x, v2.y);
                    af[wd][ks][3] = p16(v3.x, v3.y);
                }
            }
            #pragma unroll 1
            for (int j = 0; j < 18; j++) {
                const int cq = cs * 18 + j;
                float2 bb = *(const float2*)&BQs[cq * 8 + 2 * tg];
                float c[2][4];
                c[0][0] = bb.x; c[0][1] = bb.y; c[0][2] = bb.x; c[0][3] = bb.y;
                c[1][0] = bb.x; c[1][1] = bb.y; c[1][2] = bb.x; c[1][3] = bb.y;
                const u32* bp = PQG + (size_t)cq * 384 + ln * 2;
                #pragma unroll
                for (int ks = 0; ks < 6; ks++) {
                    uint2 bv = __ldg((const uint2*)(bp + ks * 64));
                    mma16(c[0][0], c[0][1], c[0][2], c[0][3],
                          af[0][ks][0], af[0][ks][1], af[0][ks][2], af[0][ks][3],
                          bv.x, bv.y);
                    mma16(c[1][0], c[1][1], c[1][2], c[1][3],
                          af[1][ks][0], af[1][ks][1], af[1][ks][2], af[1][ks][3],
                          bv.x, bv.y);
                }
                // map col -> (sec, h, d) once (same across windows / row halves)
                int col = cq * 8 + 2 * tg;
                int sec = (col >= 192) ? 2 : (col >= 96 ? 1 : 0);
                int rem = col - sec * 96;
                int h   = (rem * 171) >> 11;
                int d   = rem - h * 12;
                float vs = (sec == 0) ? SCALE : 1.f;   // fold softmax scale into Q
                #pragma unroll
                for (int wd = 0; wd < 2; wd++) {
                    int wb = (wp * 2 + wd) * 3072;
                    qkv_store_pair(QF, wb, sec, h, d, gi, 0, c[wd][0] * vs, c[wd][1] * vs);
                    qkv_store_pair(QF, wb, sec, h, d, gi, 1, c[wd][2] * vs, c[wd][3] * vs);
                }
            }
        }
        __syncthreads();

        // ================= Attention: tensor-core S and PV =================
        {
            const int aw = wid;              // warp = window
            const int wb = aw * 3072;
            const float* mrow = mask + (size_t)((g * 8 + aw) % L_DIM) * 256;
            float2 mk00 = *(const float2*)(mrow + gi * 16 + 2 * tg);
            float2 mk01 = *(const float2*)(mrow + gi * 16 + 8 + 2 * tg);
            float2 mk10 = *(const float2*)(mrow + (gi + 8) * 16 + 2 * tg);
            float2 mk11 = *(const float2*)(mrow + (gi + 8) * 16 + 8 + 2 * tg);

            #pragma unroll 1
            for (int h = 0; h < 8; h++) {
                const int bf = wb + h * 192;          // full slots
                const int bpp = bf + 1536;            // partial slots
                u32 qa0 = QF[bf + ln],        qa1 = QF[bf + 32 + ln];
                u32 qa2 = QF[bpp + ln],       qa3 = QF[bpp + 32 + ln];
                u32 kb00 = QF[bf + 64 + ln],  kb01 = QF[bpp + 64 + ln];
                u32 kb10 = QF[bf + 96 + ln],  kb11 = QF[bpp + 96 + ln];

                const float* rb = RBG + h * 256;
                float2 b00 = __ldg((const float2*)(rb + gi * 16 + 2 * tg));
                float2 b01 = __ldg((const float2*)(rb + gi * 16 + 8 + 2 * tg));
                float2 b10 = __ldg((const float2*)(rb + (gi + 8) * 16 + 2 * tg));
                float2 b11 = __ldg((const float2*)(rb + (gi + 8) * 16 + 8 + 2 * tg));

                float c00 = mk00.x + b00.x, c01 = mk00.y + b00.y;
                float c02 = mk10.x + b10.x, c03 = mk10.y + b10.y;
                float c10 = mk01.x + b01.x, c11 = mk01.y + b01.y;
                float c12 = mk11.x + b11.x, c13 = mk11.y + b11.y;
                mma16(c00, c01, c02, c03, qa0, qa1, qa2, qa3, kb00, kb01);
                mma16(c10, c11, c12, c13, qa0, qa1, qa2, qa3, kb10, kb11);

                // softmax over 16 cols: 4 in-lane + quad shuffle
                float mlo = fmaxf(fmaxf(c00, c01), fmaxf(c10, c11));
                float mhi = fmaxf(fmaxf(c02, c03), fmaxf(c12, c13));
                mlo = fmaxf(mlo, __shfl_xor_sync(0xffffffffu, mlo, 1));
                mlo = fmaxf(mlo, __shfl_xor_sync(0xffffffffu, mlo, 2));
                mhi = fmaxf(mhi, __shfl_xor_sync(0xffffffffu, mhi, 1));
                mhi = fmaxf(mhi, __shfl_xor_sync(0xffffffffu, mhi, 2));
                float e00 = __expf(c00 - mlo), e01 = __expf(c01 - mlo);
                float e10 = __expf(c10 - mlo), e11 = __expf(c11 - mlo);
                float e02 = __expf(c02 - mhi), e03 = __expf(c03 - mhi);
                float e12 = __expf(c12 - mhi), e13 = __expf(c13 - mhi);
                float slo = (e00 + e01) + (e10 + e11);
                float shi = (e02 + e03) + (e12 + e13);
                slo += __shfl_xor_sync(0xffffffffu, slo, 1);
                slo += __shfl_xor_sync(0xffffffffu, slo, 2);
                shi += __shfl_xor_sync(0xffffffffu, shi, 1);
                shi += __shfl_xor_sync(0xffffffffu, shi, 2);
                float invlo = __fdividef(1.f, slo);
                float invhi = __fdividef(1.f, shi);

                // P frags straight from registers (S C-layout == PV A-layout)
                u32 pa0 = p16(e00, e01), pa1 = p16(e02, e03);
                u32 pa2 = p16(e10, e11), pa3 = p16(e12, e13);

                u32 vb00 = QF[bf + 128 + ln],  vb01 = QF[bf + 160 + ln];
                u32 vb10 = QF[bpp + 128 + ln], vb11 = QF[bpp + 160 + ln];
                float o00 = 0, o01 = 0, o02 = 0, o03 = 0;
                float o10 = 0, o11 = 0, o12 = 0, o13 = 0;
                mma16(o00, o01, o02, o03, pa0, pa1, pa2, pa3, vb00, vb01);
                mma16(o10, o11, o12, o13, pa0, pa1, pa2, pa3, vb10, vb11);

                // store attn-out in proj-A-fragment order (AF aliases QF prefix)
                int col0 = h * 12 + 2 * tg;
                int ks0  = col0 >> 4, cm0 = col0 & 15;
                int cr0  = (cm0 >= 8) ? 2 : 0;
                int lt0  = gi * 4 + ((cm0 & 7) >> 1);
                QF[wb + (ks0 * 4 + cr0) * 32 + lt0]     = p16(o00 * invlo, o01 * invlo);
                QF[wb + (ks0 * 4 + cr0 + 1) * 32 + lt0] = p16(o02 * invhi, o03 * invhi);
                if (tg < 2) {
                    int col1 = col0 + 8;
                    int ks1  = col1 >> 4, cm1 = col1 & 15;
                    int cr1  = (cm1 >= 8) ? 2 : 0;
                    int lt1  = gi * 4 + ((cm1 & 7) >> 1);
                    QF[wb + (ks1 * 4 + cr1) * 32 + lt1]     = p16(o10 * invlo, o11 * invlo);
                    QF[wb + (ks1 * 4 + cr1 + 1) * 32 + lt1] = p16(o12 * invhi, o13 * invhi);
                }
            }
        }
        __syncthreads();

        // ================= Proj GEMM (A frags directly from AF) =================
        {
            u32 pf[2][6][4];
            #pragma unroll
            for (int wd = 0; wd < 2; wd++) {
                const int wb = (wp * 2 + wd) * 3072;
                #pragma unroll
                for (int ks = 0; ks < 6; ks++) {
                    pf[wd][ks][0] = QF[wb + (ks * 4 + 0) * 32 + ln];
                    pf[wd][ks][1] = QF[wb + (ks * 4 + 1) * 32 + ln];
                    pf[wd][ks][2] = QF[wb + (ks * 4 + 2) * 32 + ln];
                    pf[wd][ks][3] = QF[wb + (ks * 4 + 3) * 32 + ln];
                }
            }
            #pragma unroll 1
            for (int j = 0; j < 6; j++) {
                const int cq = cs * 6 + j;
                float2 bb = *(const float2*)&BPs[cq * 8 + 2 * tg];
                float c[2][4];
                c[0][0] = bb.x; c[0][1] = bb.y; c[0][2] = bb.x; c[0][3] = bb.y;
                c[1][0] = bb.x; c[1][1] = bb.y; c[1][2] = bb.x; c[1][3] = bb.y;
                const u32* bp = PRJG + (size_t)cq * 384 + ln * 2;
                #pragma unroll
                for (int ks = 0; ks < 6; ks++) {
                    uint2 bv = __ldg((const uint2*)(bp + ks * 64));
                    mma16(c[0][0], c[0][1], c[0][2], c[0][3],
                          pf[0][ks][0], pf[0][ks][1], pf[0][ks][2], pf[0][ks][3],
                          bv.x, bv.y);
                    mma16(c[1][0], c[1][1], c[1][2], c[1][3],
                          pf[1][ks][0], pf[1][ks][1], pf[1][ks][2], pf[1][ks][3],
                          bv.x, bv.y);
                }
                #pragma unroll
                for (int wd = 0; wd < 2; wd++) {
                    float* og = out + ((size_t)g * 128 + (wp * 2 + wd) * 16 + gi) * 96
                                    + cq * 8 + 2 * tg;
                    *(float2*)og            = make_float2(c[wd][0], c[wd][1]);
                    *(float2*)(og + 8 * 96) = make_float2(c[wd][2], c[wd][3]);
                }
            }
        }
        __syncthreads();   // QF reuse by next tile
    }
}

extern "C" void kernel_launch(void* const* d_in, const int* in_sizes, int n_in,
                              void* d_out, int out_size)
{
    const float* x          = (const float*)d_in[0];
    const float* mask       = (const float*)d_in[1];
    const float* qkv_w      = (const float*)d_in[2];
    const float* qkv_b      = (const float*)d_in[3];
    const float* proj_w     = (const float*)d_in[4];
    const float* proj_b     = (const float*)d_in[5];
    const float* bias_table = (const float*)d_in[6];
    float* out = (float*)d_out;

    int sms = 148;
    cudaDeviceGetAttribute(&sms, cudaDevAttrMultiProcessorCount, 0);
    cudaFuncSetAttribute(win_attn_kernel,
                         cudaFuncAttributeMaxDynamicSharedMemorySize, SMEM_BYTES);

    win_attn_kernel<<<2 * sms, 256, SMEM_BYTES>>>(x, mask, qkv_w, qkv_b,
                                                  proj_w, proj_b, bias_table, out);
}

// round 11
// speedup vs baseline: 1.7912x; 1.0402x over previous
#include <cuda_runtime.h>
#include <cuda_fp16.h>

// WindowAttention: fully tensor-core (fp16 m16n8k16), ldmatrix-native SMEM.
// 50176 windows of [16 tok, 96 ch], H=8, D=12. 8 warps/CTA, 2 CTAs/SM, tile=8 windows.
// QF per window: 8 heads x 384 u32 { Q[16][8u32] | K | V } row-major halfs.
//   pad slots 6,7 of each row: zero, except V slot6 = (1.0h, 0) -> ones col d=12
//   (PV mma then emits the softmax row-sum at col 12).
// AF (attn-out, proj-A-frag order) aliases first 768 u32 of each window block.

#define NWIN   50176
#define NTILES (NWIN / 8)      // 6272
#define L_DIM  3136
#define SCALE  0.28867513459481287f

#define QF_U32   24576                 // 8 windows * 3072
#define OFF_BQ   (QF_U32 * 4)          // 98304: qkv_bias 288 f32
#define OFF_BP   (OFF_BQ + 1152)       // proj_bias 96 f32
#define SMEM_BYTES (OFF_BP + 384)      // 99840

typedef unsigned int u32;

__device__ u32   PQG[36 * 6 * 64];     // QKV B-pack (fp16 pairs)
__device__ u32   PRJG[12 * 6 * 64];    // proj B-pack
__device__ float RBG[8 * 16 * 16];     // rel-bias [h][i][j]

__device__ __forceinline__ u32 p16(float a, float b) {
    __half2 h = __floats2half2_rn(a, b);
    return *(u32*)&h;
}
__device__ __forceinline__ u32 smem_u32(const void* p) {
    u32 a;
    asm("{ .reg .u64 t; cvta.to.shared.u64 t, %1; cvt.u32.u64 %0, t; }" : "=r"(a) : "l"(p));
    return a;
}
__device__ __forceinline__ void mma16(float& c0, float& c1, float& c2, float& c3,
                                      u32 a0, u32 a1, u32 a2, u32 a3,
                                      u32 b0, u32 b1) {
    asm volatile(
        "mma.sync.aligned.m16n8k16.row.col.f32.f16.f16.f32 "
        "{%0,%1,%2,%3}, {%4,%5,%6,%7}, {%8,%9}, {%0,%1,%2,%3};"
        : "+f"(c0), "+f"(c1), "+f"(c2), "+f"(c3)
        : "r"(a0), "r"(a1), "r"(a2), "r"(a3), "r"(b0), "r"(b1));
}
__device__ __forceinline__ void ldsm4(u32& r0, u32& r1, u32& r2, u32& r3, u32 a) {
    asm volatile("ldmatrix.sync.aligned.m8n8.x4.shared.b16 {%0,%1,%2,%3}, [%4];"
        : "=r"(r0), "=r"(r1), "=r"(r2), "=r"(r3) : "r"(a));
}
__device__ __forceinline__ void ldsm4t(u32& r0, u32& r1, u32& r2, u32& r3, u32 a) {
    asm volatile("ldmatrix.sync.aligned.m8n8.x4.trans.shared.b16 {%0,%1,%2,%3}, [%4];"
        : "=r"(r0), "=r"(r1), "=r"(r2), "=r"(r3) : "r"(a));
}

__global__ __launch_bounds__(256, 2)
void win_attn_kernel(const float* __restrict__ x,
                     const float* __restrict__ mask,
                     const float* __restrict__ qkv_w,
                     const float* __restrict__ qkv_b,
                     const float* __restrict__ proj_w,
                     const float* __restrict__ proj_b,
                     const float* __restrict__ bias_table,
                     float* __restrict__ out)
{
    extern __shared__ char smb[];
    u32*   QF  = (u32*)smb;
    float* BQs = (float*)(smb + OFF_BQ);
    float* BPs = (float*)(smb + OFF_BP);
    const u32 sb = smem_u32(smb);

    const int t = threadIdx.x;

    // ---- One-time staging ----
    for (int i = t; i < QF_U32; i += 256) {
        int off = i % 3072, r = off % 384;
        int sec = r >> 7, slot = r & 7;
        QF[i] = (sec == 2 && slot == 6) ? 0x00003C00u : 0u;   // V d12 = 1.0h
    }
    for (int i = t; i < 36 * 6 * 32; i += 256) {
        int cq = i / 192, r = i % 192, ks = r / 32, lnn = r % 32;
        int gg = lnn >> 2, tt = lnn & 3;
        int k0 = ks * 16 + 2 * tt, n = cq * 8 + gg;
        PQG[i * 2 + 0] = p16(qkv_w[k0 * 288 + n],       qkv_w[(k0 + 1) * 288 + n]);
        PQG[i * 2 + 1] = p16(qkv_w[(k0 + 8) * 288 + n], qkv_w[(k0 + 9) * 288 + n]);
    }
    for (int i = t; i < 12 * 6 * 32; i += 256) {
        int cq = i / 192, r = i % 192, ks = r / 32, lnn = r % 32;
        int gg = lnn >> 2, tt = lnn & 3;
        int k0 = ks * 16 + 2 * tt, n = cq * 8 + gg;
        PRJG[i * 2 + 0] = p16(proj_w[k0 * 96 + n],       proj_w[(k0 + 1) * 96 + n]);
        PRJG[i * 2 + 1] = p16(proj_w[(k0 + 8) * 96 + n], proj_w[(k0 + 9) * 96 + n]);
    }
    for (int i = t; i < 2048; i += 256) {
        int h = i >> 8, ii = (i >> 4) & 15, jj = i & 15;
        int d0 = (ii & 3)  - (jj & 3)  + 3;
        int d1 = (ii >> 2) - (jj >> 2) + 3;
        RBG[i] = bias_table[(d0 * 7 + d1) * 8 + h];
    }
    for (int i = t; i < 288; i += 256) BQs[i] = qkv_b[i];
    if (t < 96) BPs[t] = proj_b[t];
    __syncthreads();

    const int wid = t >> 5;
    const int ln  = t & 31;
    const int gi  = ln >> 2;
    const int tg  = ln & 3;
    const int wp  = wid >> 1;       // window pair for GEMM phases
    const int cs  = wid & 1;        // chunk half

    // ldmatrix lane byte-offsets (within a head block)
    const u32 offQ = (u32)((ln & 15) * 32 + ((ln >> 4) & 1) * 16);
    const u32 offK = (u32)(((ln & 7) + ((ln >> 4) << 3)) * 32 + ((ln >> 3) & 1) * 16 + 512);
    const u32 offV = offQ + 1024;
    const int srcln = (ln & ~3) | 2;      // shuffle source: lane holding col 12

    for (int g = blockIdx.x; g < NTILES; g += gridDim.x) {
        // ================= QKV GEMM -> row-major head blocks =================
        {
            u32 af[2][6][4];
            #pragma unroll
            for (int wd = 0; wd < 2; wd++) {
                const float* xr = x + ((size_t)g * 128 + (wp * 2 + wd) * 16 + gi) * 96;
                #pragma unroll
                for (int ks = 0; ks < 6; ks++) {
                    float2 v0 = *(const float2*)(xr + ks * 16 + 2 * tg);
                    float2 v1 = *(const float2*)(xr + 768 + ks * 16 + 2 * tg);
                    float2 v2 = *(const float2*)(xr + ks * 16 + 2 * tg + 8);
                    float2 v3 = *(const float2*)(xr + 768 + ks * 16 + 2 * tg + 8);
                    af[wd][ks][0] = p16(v0.x, v0.y);
                    af[wd][ks][1] = p16(v1.x, v1.y);
                    af[wd][ks][2] = p16(v2.x, v2.y);
                    af[wd][ks][3] = p16(v3.x, v3.y);
                }
            }
            // refresh pad slots of heads 0,1 (trampled by last tile's AF)
            for (int i = t; i < 1536; i += 256) {
                int win = i / 192, r = i % 192;
                int h = r / 96, r2 = r % 96, sec = r2 >> 5, r3 = r2 & 31;
                int j = r3 >> 1, slot = 6 + (r3 & 1);
                QF[win * 3072 + h * 384 + sec * 128 + j * 8 + slot] =
                    (sec == 2 && slot == 6) ? 0x00003C00u : 0u;
            }
            #pragma unroll 1
            for (int j = 0; j < 18; j++) {
                const int cq = cs * 18 + j;
                float2 bb = *(const float2*)&BQs[cq * 8 + 2 * tg];
                float c[2][4];
                c[0][0] = bb.x; c[0][1] = bb.y; c[0][2] = bb.x; c[0][3] = bb.y;
                c[1][0] = bb.x; c[1][1] = bb.y; c[1][2] = bb.x; c[1][3] = bb.y;
                const u32* bp = PQG + (size_t)cq * 384 + ln * 2;
                #pragma unroll
                for (int ks = 0; ks < 6; ks++) {
                    uint2 bv = __ldg((const uint2*)(bp + ks * 64));
                    mma16(c[0][0], c[0][1], c[0][2], c[0][3],
                          af[0][ks][0], af[0][ks][1], af[0][ks][2], af[0][ks][3],
                          bv.x, bv.y);
                    mma16(c[1][0], c[1][1], c[1][2], c[1][3],
                          af[1][ks][0], af[1][ks][1], af[1][ks][2], af[1][ks][3],
                          bv.x, bv.y);
                }
                int col = cq * 8 + 2 * tg;
                int sec = (col >= 192) ? 2 : (col >= 96 ? 1 : 0);
                int rem = col - sec * 96;
                int h   = (rem * 171) >> 11;
                int d   = rem - h * 12;
                float vs = (sec == 0) ? SCALE : 1.f;     // fold softmax scale into Q
                int base = h * 384 + sec * 128 + (d >> 1);
                #pragma unroll
                for (int wd = 0; wd < 2; wd++) {
                    int wb = (wp * 2 + wd) * 3072;
                    QF[wb + base + gi * 8]       = p16(c[wd][0] * vs, c[wd][1] * vs);
                    QF[wb + base + (gi + 8) * 8] = p16(c[wd][2] * vs, c[wd][3] * vs);
                }
            }
        }
        __syncthreads();

        // ================= Attention: ldmatrix + mma, sum via ones-col =========
        {
            const int aw = wid;                    // warp = window
            const int wb = aw * 3072;
            u32 hbase = sb + (u32)wb * 4;          // byte base of head 0 block
            const float* mrow = mask + (size_t)((g * 8 + aw) % L_DIM) * 256;
            float2 mk00 = *(const float2*)(mrow + gi * 16 + 2 * tg);
            float2 mk01 = *(const float2*)(mrow + gi * 16 + 8 + 2 * tg);
            float2 mk10 = *(const float2*)(mrow + (gi + 8) * 16 + 2 * tg);
            float2 mk11 = *(const float2*)(mrow + (gi + 8) * 16 + 8 + 2 * tg);

            #pragma unroll 1
            for (int h = 0; h < 8; h++) {
                u32 qa0, qa1, qa2, qa3, k0, k1, k2, k3, v0, v1, v2, v3;
                ldsm4 (qa0, qa1, qa2, qa3, hbase + offQ);
                ldsm4 (k0, k1, k2, k3, hbase + offK);
                ldsm4t(v0, v1, v2, v3, hbase + offV);

                const float* rb = RBG + h * 256;
                float2 b00 = __ldg((const float2*)(rb + gi * 16 + 2 * tg));
                float2 b01 = __ldg((const float2*)(rb + gi * 16 + 8 + 2 * tg));
                float2 b10 = __ldg((const float2*)(rb + (gi + 8) * 16 + 2 * tg));
                float2 b11 = __ldg((const float2*)(rb + (gi + 8) * 16 + 8 + 2 * tg));

                float c00 = mk00.x + b00.x, c01 = mk00.y + b00.y;
                float c02 = mk10.x + b10.x, c03 = mk10.y + b10.y;
                float c10 = mk01.x + b01.x, c11 = mk01.y + b01.y;
                float c12 = mk11.x + b11.x, c13 = mk11.y + b11.y;
                mma16(c00, c01, c02, c03, qa0, qa1, qa2, qa3, k0, k1);
                mma16(c10, c11, c12, c13, qa0, qa1, qa2, qa3, k2, k3);

                // no max-subtraction: |scores| <= ~6 (mask-dominated), exp is safe
                float e00 = __expf(c00), e01 = __expf(c01);
                float e02 = __expf(c02), e03 = __expf(c03);
                float e10 = __expf(c10), e11 = __expf(c11);
                float e12 = __expf(c12), e13 = __expf(c13);

                u32 pa0 = p16(e00, e01), pa1 = p16(e02, e03);
                u32 pa2 = p16(e10, e11), pa3 = p16(e12, e13);

                float o00 = 0, o01 = 0, o02 = 0, o03 = 0;
                float o10 = 0, o11 = 0, o12 = 0, o13 = 0;
                mma16(o00, o01, o02, o03, pa0, pa1, pa2, pa3, v0, v1);
                mma16(o10, o11, o12, o13, pa0, pa1, pa2, pa3, v2, v3);

                // row sums arrive at col 12 (ones column) -> lane tg=2 regs o10/o12
                float slo = __shfl_sync(0xffffffffu, o10, srcln);
                float shi = __shfl_sync(0xffffffffu, o12, srcln);
                float invlo = __fdividef(1.f, slo);
                float invhi = __fdividef(1.f, shi);

                // store attn-out in proj-A-fragment order (AF aliases QF prefix)
                int col0 = h * 12 + 2 * tg;
                int ks0  = col0 >> 4, cm0 = col0 & 15;
                int cr0  = (cm0 >= 8) ? 2 : 0;
                int lt0  = gi * 4 + ((cm0 & 7) >> 1);
                QF[wb + (ks0 * 4 + cr0) * 32 + lt0]     = p16(o00 * invlo, o01 * invlo);
                QF[wb + (ks0 * 4 + cr0 + 1) * 32 + lt0] = p16(o02 * invhi, o03 * invhi);
                if (tg < 2) {
                    int col1 = col0 + 8;
                    int ks1  = col1 >> 4, cm1 = col1 & 15;
                    int cr1  = (cm1 >= 8) ? 2 : 0;
                    int lt1  = gi * 4 + ((cm1 & 7) >> 1);
                    QF[wb + (ks1 * 4 + cr1) * 32 + lt1]     = p16(o10 * invlo, o11 * invlo);
                    QF[wb + (ks1 * 4 + cr1 + 1) * 32 + lt1] = p16(o12 * invhi, o13 * invhi);
                }
                hbase += 1536;
            }
        }
        __syncthreads();

        // ================= Proj GEMM (A frags directly from AF) =================
        {
            u32 pf[2][6][4];
            #pragma unroll
            for (int wd = 0; wd < 2; wd++) {
                const int wb = (wp * 2 + wd) * 3072;
                #pragma unroll
                for (int ks = 0; ks < 6; ks++) {
                    pf[wd][ks][0] = QF[wb + (ks * 4 + 0) * 32 + ln];
                    pf[wd][ks][1] = QF[wb + (ks * 4 + 1) * 32 + ln];
                    pf[wd][ks][2] = QF[wb + (ks * 4 + 2) * 32 + ln];
                    pf[wd][ks][3] = QF[wb + (ks * 4 + 3) * 32 + ln];
                }
            }
            #pragma unroll 1
            for (int j = 0; j < 6; j++) {
                const int cq = cs * 6 + j;
                float2 bb = *(const float2*)&BPs[cq * 8 + 2 * tg];
                float c[2][4];
                c[0][0] = bb.x; c[0][1] = bb.y; c[0][2] = bb.x; c[0][3] = bb.y;
                c[1][0] = bb.x; c[1][1] = bb.y; c[1][2] = bb.x; c[1][3] = bb.y;
                const u32* bp = PRJG + (size_t)cq * 384 + ln * 2;
                #pragma unroll
                for (int ks = 0; ks < 6; ks++) {
                    uint2 bv = __ldg((const uint2*)(bp + ks * 64));
                    mma16(c[0][0], c[0][1], c[0][2], c[0][3],
                          pf[0][ks][0], pf[0][ks][1], pf[0][ks][2], pf[0][ks][3],
                          bv.x, bv.y);
                    mma16(c[1][0], c[1][1], c[1][2], c[1][3],
                          pf[1][ks][0], pf[1][ks][1], pf[1][ks][2], pf[1][ks][3],
                          bv.x, bv.y);
                }
                #pragma unroll
                for (int wd = 0; wd < 2; wd++) {
                    float* og = out + ((size_t)g * 128 + (wp * 2 + wd) * 16 + gi) * 96
                                    + cq * 8 + 2 * tg;
                    *(float2*)og            = make_float2(c[wd][0], c[wd][1]);
                    *(float2*)(og + 8 * 96) = make_float2(c[wd][2], c[wd][3]);
                }
            }
        }
        __syncthreads();   // QF reuse by next tile
    }
}

extern "C" void kernel_launch(void* const* d_in, const int* in_sizes, int n_in,
                              void* d_out, int out_size)
{
    const float* x          = (const float*)d_in[0];
    const float* mask       = (const float*)d_in[1];
    const float* qkv_w      = (const float*)d_in[2];
    const float* qkv_b      = (const float*)d_in[3];
    const float* proj_w     = (const float*)d_in[4];
    const float* proj_b     = (const float*)d_in[5];
    const float* bias_table = (const float*)d_in[6];
    float* out = (float*)d_out;

    int sms = 148;
    cudaDeviceGetAttribute(&sms, cudaDevAttrMultiProcessorCount, 0);
    cudaFuncSetAttribute(win_attn_kernel,
                         cudaFuncAttributeMaxDynamicSharedMemorySize, SMEM_BYTES);

    win_attn_kernel<<<2 * sms, 256, SMEM_BYTES>>>(x, mask, qkv_w, qkv_b,
                                                  proj_w, proj_b, bias_table, out);
}

// round 12
// speedup vs baseline: 1.9589x; 1.0936x over previous
#include <cuda_runtime.h>
#include <cuda_fp16.h>

// WindowAttention: fully tensor-core (fp16 m16n8k16), ldmatrix-native SMEM.
// 50176 windows of [16 tok, 96 ch], H=8, D=12. 8 warps/CTA, 2 CTAs/SM, tile=8 windows.
// QF per window: 8 heads x 384 u32 { Q[16][8u32] | K | V } row-major halfs.
//   pad slots 6,7 of each row zero, except V slot6 = (1.0h,0) -> ones col d=12
//   (PV mma emits the softmax row-sum at col 12).
// AF (attn-out, proj-A frags) aliases first 768 u32 of each window block,
//   layout [ks][pair][lane][2] so stores are STS.64 / loads are LDS.64.

#define NWIN   50176
#define NTILES (NWIN / 8)      // 6272
#define L_DIM  3136
#define SCALE  0.28867513459481287f

#define QF_U32   24576                 // 8 windows * 3072
#define OFF_BQ   (QF_U32 * 4)          // 98304: qkv_bias 288 f32
#define OFF_BP   (OFF_BQ + 1152)       // proj_bias 96 f32
#define SMEM_BYTES (OFF_BP + 384)      // 99840

typedef unsigned int u32;

__device__ u32 PQG[36 * 6 * 64];       // QKV B-pack: [cq][ks2][ln][4]
__device__ u32 PRJG[12 * 6 * 64];      // proj B-pack, same scheme
__device__ u32 RBH[8 * 128];           // rel-bias half2 [h][i][j2]

__device__ __forceinline__ u32 p16(float a, float b) {
    __half2 h = __floats2half2_rn(a, b);
    return *(u32*)&h;
}
__device__ __forceinline__ u32 smem_u32(const void* p) {
    u32 a;
    asm("{ .reg .u64 t; cvta.to.shared.u64 t, %1; cvt.u32.u64 %0, t; }" : "=r"(a) : "l"(p));
    return a;
}
__device__ __forceinline__ void mma16(float& c0, float& c1, float& c2, float& c3,
                                      u32 a0, u32 a1, u32 a2, u32 a3,
                                      u32 b0, u32 b1) {
    asm volatile(
        "mma.sync.aligned.m16n8k16.row.col.f32.f16.f16.f32 "
        "{%0,%1,%2,%3}, {%4,%5,%6,%7}, {%8,%9}, {%0,%1,%2,%3};"
        : "+f"(c0), "+f"(c1), "+f"(c2), "+f"(c3)
        : "r"(a0), "r"(a1), "r"(a2), "r"(a3), "r"(b0), "r"(b1));
}
__device__ __forceinline__ void ldsm4(u32& r0, u32& r1, u32& r2, u32& r3, u32 a) {
    asm volatile("ldmatrix.sync.aligned.m8n8.x4.shared.b16 {%0,%1,%2,%3}, [%4];"
        : "=r"(r0), "=r"(r1), "=r"(r2), "=r"(r3) : "r"(a));
}
__device__ __forceinline__ void ldsm4t(u32& r0, u32& r1, u32& r2, u32& r3, u32 a) {
    asm volatile("ldmatrix.sync.aligned.m8n8.x4.trans.shared.b16 {%0,%1,%2,%3}, [%4];"
        : "=r"(r0), "=r"(r1), "=r"(r2), "=r"(r3) : "r"(a));
}

__global__ __launch_bounds__(256, 2)
void win_attn_kernel(const float* __restrict__ x,
                     const float* __restrict__ mask,
                     const float* __restrict__ qkv_w,
                     const float* __restrict__ qkv_b,
                     const float* __restrict__ proj_w,
                     const float* __restrict__ proj_b,
                     const float* __restrict__ bias_table,
                     float* __restrict__ out)
{
    extern __shared__ char smb[];
    u32*   QF  = (u32*)smb;
    float* BQs = (float*)(smb + OFF_BQ);
    float* BPs = (float*)(smb + OFF_BP);
    const u32 sb = smem_u32(smb);

    const int t = threadIdx.x;

    // ---- One-time staging ----
    for (int i = t; i < QF_U32; i += 256) {
        int off = i % 3072, r = off % 384;
        int sec = r >> 7, slot = r & 7;
        QF[i] = (sec == 2 && slot == 6) ? 0x00003C00u : 0u;   // V d12 = 1.0h
    }
    for (int i = t; i < 36 * 6 * 32; i += 256) {
        int cq = i / 192, r = i % 192, ks = r / 32, lnn = r % 32;
        int gg = lnn >> 2, tt = lnn & 3;
        int k0 = ks * 16 + 2 * tt, n = cq * 8 + gg;
        int dst = cq * 384 + (ks >> 1) * 128 + lnn * 4 + (ks & 1) * 2;
        PQG[dst + 0] = p16(qkv_w[k0 * 288 + n],       qkv_w[(k0 + 1) * 288 + n]);
        PQG[dst + 1] = p16(qkv_w[(k0 + 8) * 288 + n], qkv_w[(k0 + 9) * 288 + n]);
    }
    for (int i = t; i < 12 * 6 * 32; i += 256) {
        int cq = i / 192, r = i % 192, ks = r / 32, lnn = r % 32;
        int gg = lnn >> 2, tt = lnn & 3;
        int k0 = ks * 16 + 2 * tt, n = cq * 8 + gg;
        int dst = cq * 384 + (ks >> 1) * 128 + lnn * 4 + (ks & 1) * 2;
        PRJG[dst + 0] = p16(proj_w[k0 * 96 + n],       proj_w[(k0 + 1) * 96 + n]);
        PRJG[dst + 1] = p16(proj_w[(k0 + 8) * 96 + n], proj_w[(k0 + 9) * 96 + n]);
    }
    for (int i = t; i < 1024; i += 256) {
        int h = i >> 7, ii = (i >> 3) & 15, j2 = i & 7;
        int j0 = 2 * j2, j1 = 2 * j2 + 1;
        int d00 = (ii & 3) - (j0 & 3) + 3, d10 = (ii >> 2) - (j0 >> 2) + 3;
        int d01 = (ii & 3) - (j1 & 3) + 3, d11 = (ii >> 2) - (j1 >> 2) + 3;
        RBH[i] = p16(bias_table[(d00 * 7 + d10) * 8 + h],
                     bias_table[(d01 * 7 + d11) * 8 + h]);
    }
    for (int i = t; i < 288; i += 256) BQs[i] = qkv_b[i];
    if (t < 96) BPs[t] = proj_b[t];
    __syncthreads();

    const int wid = t >> 5;
    const int ln  = t & 31;
    const int gi  = ln >> 2;
    const int tg  = ln & 3;
    const int wp  = wid >> 1;       // window pair for GEMM phases
    const int cs  = wid & 1;        // chunk half

    // ldmatrix lane byte-offsets (within a head block)
    const u32 offQ = (u32)((ln & 15) * 32 + ((ln >> 4) & 1) * 16);
    const u32 offK = (u32)(((ln & 7) + ((ln >> 4) << 3)) * 32 + ((ln >> 3) & 1) * 16 + 512);
    const u32 offV = offQ + 1024;
    const int srcln = (ln & ~3) | 2;      // shuffle source: lane holding col 12

    for (int g = blockIdx.x; g < NTILES; g += gridDim.x) {
        // ================= QKV GEMM -> row-major head blocks =================
        {
            u32 af[2][6][4];
            #pragma unroll
            for (int wd = 0; wd < 2; wd++) {
                const float* xr = x + ((size_t)g * 128 + (wp * 2 + wd) * 16 + gi) * 96;
                #pragma unroll
                for (int ks = 0; ks < 6; ks++) {
                    float2 v0 = *(const float2*)(xr + ks * 16 + 2 * tg);
                    float2 v1 = *(const float2*)(xr + 768 + ks * 16 + 2 * tg);
                    float2 v2 = *(const float2*)(xr + ks * 16 + 2 * tg + 8);
                    float2 v3 = *(const float2*)(xr + 768 + ks * 16 + 2 * tg + 8);
                    af[wd][ks][0] = p16(v0.x, v0.y);
                    af[wd][ks][1] = p16(v1.x, v1.y);
                    af[wd][ks][2] = p16(v2.x, v2.y);
                    af[wd][ks][3] = p16(v3.x, v3.y);
                }
            }
            // refresh pad slots of heads 0,1 (trampled by last tile's AF)
            for (int i = t; i < 1536; i += 256) {
                int win = i / 192, r = i % 192;
                int h = r / 96, r2 = r % 96, sec = r2 >> 5, r3 = r2 & 31;
                int j = r3 >> 1, slot = 6 + (r3 & 1);
                QF[win * 3072 + h * 384 + sec * 128 + j * 8 + slot] =
                    (sec == 2 && slot == 6) ? 0x00003C00u : 0u;
            }
            #pragma unroll 2
            for (int j = 0; j < 18; j++) {
                const int cq = cs * 18 + j;
                float2 bb = *(const float2*)&BQs[cq * 8 + 2 * tg];
                float c[2][4];
                c[0][0] = bb.x; c[0][1] = bb.y; c[0][2] = bb.x; c[0][3] = bb.y;
                c[1][0] = bb.x; c[1][1] = bb.y; c[1][2] = bb.x; c[1][3] = bb.y;
                const u32* bp = PQG + (size_t)cq * 384 + ln * 4;
                #pragma unroll
                for (int ks2 = 0; ks2 < 3; ks2++) {
                    uint4 bv = __ldg((const uint4*)(bp + ks2 * 128));
                    mma16(c[0][0], c[0][1], c[0][2], c[0][3],
                          af[0][2*ks2][0], af[0][2*ks2][1], af[0][2*ks2][2], af[0][2*ks2][3],
                          bv.x, bv.y);
                    mma16(c[1][0], c[1][1], c[1][2], c[1][3],
                          af[1][2*ks2][0], af[1][2*ks2][1], af[1][2*ks2][2], af[1][2*ks2][3],
                          bv.x, bv.y);
                    mma16(c[0][0], c[0][1], c[0][2], c[0][3],
                          af[0][2*ks2+1][0], af[0][2*ks2+1][1], af[0][2*ks2+1][2], af[0][2*ks2+1][3],
                          bv.z, bv.w);
                    mma16(c[1][0], c[1][1], c[1][2], c[1][3],
                          af[1][2*ks2+1][0], af[1][2*ks2+1][1], af[1][2*ks2+1][2], af[1][2*ks2+1][3],
                          bv.z, bv.w);
                }
                int col = cq * 8 + 2 * tg;
                int sec = (col >= 192) ? 2 : (col >= 96 ? 1 : 0);
                int rem = col - sec * 96;
                int h   = (rem * 171) >> 11;
                int d   = rem - h * 12;
                float vs = (sec == 0) ? SCALE : 1.f;     // fold softmax scale into Q
                int base = h * 384 + sec * 128 + (d >> 1);
                #pragma unroll
                for (int wd = 0; wd < 2; wd++) {
                    int wb = (wp * 2 + wd) * 3072;
                    QF[wb + base + gi * 8]       = p16(c[wd][0] * vs, c[wd][1] * vs);
                    QF[wb + base + (gi + 8) * 8] = p16(c[wd][2] * vs, c[wd][3] * vs);
                }
            }
        }
        __syncthreads();

        // ================= Attention: ldmatrix + mma, sum via ones-col =========
        {
            const int aw = wid;                    // warp = window
            const int wb = aw * 3072;
            u32 hbase = sb + (u32)wb * 4;          // byte base of head 0 block
            const float* mrow = mask + (size_t)((g * 8 + aw) % L_DIM) * 256;
            float2 mk00 = *(const float2*)(mrow + gi * 16 + 2 * tg);
            float2 mk01 = *(const float2*)(mrow + gi * 16 + 8 + 2 * tg);
            float2 mk10 = *(const float2*)(mrow + (gi + 8) * 16 + 2 * tg);
            float2 mk11 = *(const float2*)(mrow + (gi + 8) * 16 + 8 + 2 * tg);
            const __half2* RB2 = (const __half2*)RBH;

            #pragma unroll 2
            for (int h = 0; h < 8; h++) {
                u32 qa0, qa1, qa2, qa3, k0, k1, k2, k3, v0, v1, v2, v3;
                ldsm4 (qa0, qa1, qa2, qa3, hbase + offQ);
                ldsm4 (k0, k1, k2, k3, hbase + offK);
                ldsm4t(v0, v1, v2, v3, hbase + offV);

                float2 b00 = __half22float2(__ldg(RB2 + h * 128 + gi * 8 + tg));
                float2 b01 = __half22float2(__ldg(RB2 + h * 128 + gi * 8 + tg + 4));
                float2 b10 = __half22float2(__ldg(RB2 + h * 128 + (gi + 8) * 8 + tg));
                float2 b11 = __half22float2(__ldg(RB2 + h * 128 + (gi + 8) * 8 + tg + 4));

                float c00 = mk00.x + b00.x, c01 = mk00.y + b00.y;
                float c02 = mk10.x + b10.x, c03 = mk10.y + b10.y;
                float c10 = mk01.x + b01.x, c11 = mk01.y + b01.y;
                float c12 = mk11.x + b11.x, c13 = mk11.y + b11.y;
                mma16(c00, c01, c02, c03, qa0, qa1, qa2, qa3, k0, k1);
                mma16(c10, c11, c12, c13, qa0, qa1, qa2, qa3, k2, k3);

                // no max-subtraction: |scores| <= ~6 (mask-dominated), exp is safe
                float e00 = __expf(c00), e01 = __expf(c01);
                float e02 = __expf(c02), e03 = __expf(c03);
                float e10 = __expf(c10), e11 = __expf(c11);
                float e12 = __expf(c12), e13 = __expf(c13);

                u32 pa0 = p16(e00, e01), pa1 = p16(e02, e03);
                u32 pa2 = p16(e10, e11), pa3 = p16(e12, e13);

                float o00 = 0, o01 = 0, o02 = 0, o03 = 0;
                float o10 = 0, o11 = 0, o12 = 0, o13 = 0;
                mma16(o00, o01, o02, o03, pa0, pa1, pa2, pa3, v0, v1);
                mma16(o10, o11, o12, o13, pa0, pa1, pa2, pa3, v2, v3);

                // row sums arrive at col 12 (ones column) -> lane tg=2 regs o10/o12
                float slo = __shfl_sync(0xffffffffu, o10, srcln);
                float shi = __shfl_sync(0xffffffffu, o12, srcln);
                float invlo = __fdividef(1.f, slo);
                float invhi = __fdividef(1.f, shi);

                // store attn-out in paired proj-A-frag order (AF aliases QF prefix)
                int col0 = h * 12 + 2 * tg;
                int ks0  = col0 >> 4;
                int p0   = (col0 >> 3) & 1;
                int lt0  = gi * 4 + ((col0 & 7) >> 1);
                uint2 sv0;
                sv0.x = p16(o00 * invlo, o01 * invlo);
                sv0.y = p16(o02 * invhi, o03 * invhi);
                *(uint2*)&QF[wb + ks0 * 128 + p0 * 64 + lt0 * 2] = sv0;
                if (tg < 2) {
                    int col1 = col0 + 8;
                    int ks1  = col1 >> 4;
                    int p1   = (col1 >> 3) & 1;
                    int lt1  = gi * 4 + ((col1 & 7) >> 1);
                    uint2 sv1;
                    sv1.x = p16(o10 * invlo, o11 * invlo);
                    sv1.y = p16(o12 * invhi, o13 * invhi);
                    *(uint2*)&QF[wb + ks1 * 128 + p1 * 64 + lt1 * 2] = sv1;
                }
                hbase += 1536;
            }
        }
        __syncthreads();

        // ================= Proj GEMM (A frags as LDS.64 pairs from AF) ==========
        {
            u32 pf[2][6][4];
            #pragma unroll
            for (int wd = 0; wd < 2; wd++) {
                const int wb = (wp * 2 + wd) * 3072;
                #pragma unroll
                for (int ks = 0; ks < 6; ks++) {
                    uint2 L0 = *(const uint2*)&QF[wb + ks * 128 + ln * 2];
                    uint2 L1 = *(const uint2*)&QF[wb + ks * 128 + 64 + ln * 2];
                    pf[wd][ks][0] = L0.x; pf[wd][ks][1] = L0.y;
                    pf[wd][ks][2] = L1.x; pf[wd][ks][3] = L1.y;
                }
            }
            #pragma unroll 2
            for (int j = 0; j < 6; j++) {
                const int cq = cs * 6 + j;
                float2 bb = *(const float2*)&BPs[cq * 8 + 2 * tg];
                float c[2][4];
                c[0][0] = bb.x; c[0][1] = bb.y; c[0][2] = bb.x; c[0][3] = bb.y;
                c[1][0] = bb.x; c[1][1] = bb.y; c[1][2] = bb.x; c[1][3] = bb.y;
                const u32* bp = PRJG + (size_t)cq * 384 + ln * 4;
                #pragma unroll
                for (int ks2 = 0; ks2 < 3; ks2++) {
                    uint4 bv = __ldg((const uint4*)(bp + ks2 * 128));
                    mma16(c[0][0], c[0][1], c[0][2], c[0][3],
                          pf[0][2*ks2][0], pf[0][2*ks2][1], pf[0][2*ks2][2], pf[0][2*ks2][3],
                          bv.x, bv.y);
                    mma16(c[1][0], c[1][1], c[1][2], c[1][3],
                          pf[1][2*ks2][0], pf[1][2*ks2][1], pf[1][2*ks2][2], pf[1][2*ks2][3],
                          bv.x, bv.y);
                    mma16(c[0][0], c[0][1], c[0][2], c[0][3],
                          pf[0][2*ks2+1][0], pf[0][2*ks2+1][1], pf[0][2*ks2+1][2], pf[0][2*ks2+1][3],
                          bv.z, bv.w);
                    mma16(c[1][0], c[1][1], c[1][2], c[1][3],
                          pf[1][2*ks2+1][0], pf[1][2*ks2+1][1], pf[1][2*ks2+1][2], pf[1][2*ks2+1][3],
                          bv.z, bv.w);
                }
                #pragma unroll
                for (int wd = 0; wd < 2; wd++) {
                    float* og = out + ((size_t)g * 128 + (wp * 2 + wd) * 16 + gi) * 96
                                    + cq * 8 + 2 * tg;
                    *(float2*)og            = make_float2(c[wd][0], c[wd][1]);
                    *(float2*)(og + 8 * 96) = make_float2(c[wd][2], c[wd][3]);
                }
            }
        }
        __syncthreads();   // QF reuse by next tile
    }
}

extern "C" void kernel_launch(void* const* d_in, const int* in_sizes, int n_in,
                              void* d_out, int out_size)
{
    const float* x          = (const float*)d_in[0];
    const float* mask       = (const float*)d_in[1];
    const float* qkv_w      = (const float*)d_in[2];
    const float* qkv_b      = (const float*)d_in[3];
    const float* proj_w     = (const float*)d_in[4];
    const float* proj_b     = (const float*)d_in[5];
    const float* bias_table = (const float*)d_in[6];
    float* out = (float*)d_out;

    int sms = 148;
    cudaDeviceGetAttribute(&sms, cudaDevAttrMultiProcessorCount, 0);
    cudaFuncSetAttribute(win_attn_kernel,
                         cudaFuncAttributeMaxDynamicSharedMemorySize, SMEM_BYTES);

    win_attn_kernel<<<2 * sms, 256, SMEM_BYTES>>>(x, mask, qkv_w, qkv_b,
                                                  proj_w, proj_b, bias_table, out);
}

// round 14
// speedup vs baseline: 1.9678x; 1.0045x over previous
#include <cuda_runtime.h>
#include <cuda_fp16.h>

// WindowAttention: fully tensor-core (fp16 m16n8k16), ldmatrix-native SMEM.
// 50176 windows of [16 tok, 96 ch], H=8, D=12. 4 warps/CTA, 4 CTAs/SM, tile=4 windows.
// QF per window: 8 heads x 384 u32 { Q[16 rows] | K | V }.
//   XOR swizzle: row r, slot s  ->  u32 offset 8r + (s ^ (r & 4))
//   (bijective; kills the stride-8 bank aliasing between rows r and r+4).
//   pad slots 6,7 (logical) zero, except V slot6 = (1.0h,0) -> ones col d=12
//   (PV mma emits the softmax row-sum at col 12).
// AF (attn-out, proj-A frags) aliases first 768 u32 of each window block,
//   layout [ks][pair][lane][2]: stores STS.64 / loads LDS.64 (unswizzled).

#define NWIN   50176
#define NTILES (NWIN / 4)      // 12544
#define L_DIM  3136
#define SCALE  0.28867513459481287f

#define QF_U32   12288                 // 4 windows * 3072
#define OFF_BQ   (QF_U32 * 4)          // 49152: qkv_bias 288 f32
#define OFF_BP   (OFF_BQ + 1152)       // proj_bias 96 f32
#define SMEM_BYTES (OFF_BP + 384)      // 50688

typedef unsigned int u32;

__device__ u32 PQG[36 * 6 * 64];       // QKV B-pack: [cq][ks2][ln][4]
__device__ u32 PRJG[12 * 6 * 64];      // proj B-pack, same scheme
__device__ u32 RBH[8 * 128];           // rel-bias half2 [h][i][j2]

__device__ __forceinline__ u32 p16(float a, float b) {
    __half2 h = __floats2half2_rn(a, b);
    return *(u32*)&h;
}
__device__ __forceinline__ u32 smem_u32(const void* p) {
    u32 a;
    asm("{ .reg .u64 t; cvta.to.shared.u64 t, %1; cvt.u32.u64 %0, t; }" : "=r"(a) : "l"(p));
    return a;
}
__device__ __forceinline__ void mma16(float& c0, float& c1, float& c2, float& c3,
                                      u32 a0, u32 a1, u32 a2, u32 a3,
                                      u32 b0, u32 b1) {
    asm volatile(
        "mma.sync.aligned.m16n8k16.row.col.f32.f16.f16.f32 "
        "{%0,%1,%2,%3}, {%4,%5,%6,%7}, {%8,%9}, {%0,%1,%2,%3};"
        : "+f"(c0), "+f"(c1), "+f"(c2), "+f"(c3)
        : "r"(a0), "r"(a1), "r"(a2), "r"(a3), "r"(b0), "r"(b1));
}
__device__ __forceinline__ void ldsm4(u32& r0, u32& r1, u32& r2, u32& r3, u32 a) {
    asm volatile("ldmatrix.sync.aligned.m8n8.x4.shared.b16 {%0,%1,%2,%3}, [%4];"
        : "=r"(r0), "=r"(r1), "=r"(r2), "=r"(r3) : "r"(a));
}
__device__ __forceinline__ void ldsm4t(u32& r0, u32& r1, u32& r2, u32& r3, u32 a) {
    asm volatile("ldmatrix.sync.aligned.m8n8.x4.trans.shared.b16 {%0,%1,%2,%3}, [%4];"
        : "=r"(r0), "=r"(r1), "=r"(r2), "=r"(r3) : "r"(a));
}

__global__ __launch_bounds__(128, 4)
void win_attn_kernel(const float* __restrict__ x,
                     const float* __restrict__ mask,
                     const float* __restrict__ qkv_w,
                     const float* __restrict__ qkv_b,
                     const float* __restrict__ proj_w,
                     const float* __restrict__ proj_b,
                     const float* __restrict__ bias_table,
                     float* __restrict__ out)
{
    extern __shared__ char smb[];
    u32*   QF  = (u32*)smb;
    float* BQs = (float*)(smb + OFF_BQ);
    float* BPs = (float*)(smb + OFF_BP);
    const u32 sb = smem_u32(smb);

    const int t = threadIdx.x;

    // ---- One-time staging ----
    for (int i = t; i < QF_U32; i += 128) QF[i] = 0;
    __syncthreads();
    for (int i = t; i < 512; i += 128) {            // V ones col (d=12, slot 6)
        int win = i >> 7, h = (i >> 4) & 7, row = i & 15;
        QF[win * 3072 + h * 384 + 256 + row * 8 + (6 ^ (row & 4))] = 0x00003C00u;
    }
    for (int i = t; i < 36 * 6 * 32; i += 128) {
        int cq = i / 192, r = i % 192, ks = r / 32, lnn = r % 32;
        int gg = lnn >> 2, tt = lnn & 3;
        int k0 = ks * 16 + 2 * tt, n = cq * 8 + gg;
        int dst = cq * 384 + (ks >> 1) * 128 + lnn * 4 + (ks & 1) * 2;
        PQG[dst + 0] = p16(qkv_w[k0 * 288 + n],       qkv_w[(k0 + 1) * 288 + n]);
        PQG[dst + 1] = p16(qkv_w[(k0 + 8) * 288 + n], qkv_w[(k0 + 9) * 288 + n]);
    }
    for (int i = t; i < 12 * 6 * 32; i += 128) {
        int cq = i / 192, r = i % 192, ks = r / 32, lnn = r % 32;
        int gg = lnn >> 2, tt = lnn & 3;
        int k0 = ks * 16 + 2 * tt, n = cq * 8 + gg;
        int dst = cq * 384 + (ks >> 1) * 128 + lnn * 4 + (ks & 1) * 2;
        PRJG[dst + 0] = p16(proj_w[k0 * 96 + n],       proj_w[(k0 + 1) * 96 + n]);
        PRJG[dst + 1] = p16(proj_w[(k0 + 8) * 96 + n], proj_w[(k0 + 9) * 96 + n]);
    }
    for (int i = t; i < 1024; i += 128) {
        int h = i >> 7, ii = (i >> 3) & 15, j2 = i & 7;
        int j0 = 2 * j2, j1 = 2 * j2 + 1;
        int d00 = (ii & 3) - (j0 & 3) + 3, d10 = (ii >> 2) - (j0 >> 2) + 3;
        int d01 = (ii & 3) - (j1 & 3) + 3, d11 = (ii >> 2) - (j1 >> 2) + 3;
        RBH[i] = p16(bias_table[(d00 * 7 + d10) * 8 + h],
                     bias_table[(d01 * 7 + d11) * 8 + h]);
    }
    for (int i = t; i < 288; i += 128) BQs[i] = qkv_b[i];
    if (t < 96) BPs[t] = proj_b[t];
    __syncthreads();

    const int wid = t >> 5;
    const int ln  = t & 31;
    const int gi  = ln >> 2;
    const int tg  = ln & 3;
    const int wp  = wid >> 1;       // window pair for GEMM phases
    const int cs  = wid & 1;        // chunk half
    const int xgi = gi & 4;         // epilogue slot-XOR bit (rows gi, gi+8)

    // ldmatrix lane byte-offsets (within a head block), XOR-swizzled halves
    const int rQ = ln & 15;
    const u32 offQ = (u32)(rQ * 32 + ((((ln >> 4) & 1) << 4) ^ ((rQ & 4) << 2)));
    const int rK = (ln & 7) | (((ln >> 4) & 1) << 3);
    const u32 offK = (u32)(rK * 32 + ((((ln >> 3) & 1) << 4) ^ ((rK & 4) << 2)) + 512);
    const u32 offV = offQ + 1024;
    const int srcln = (ln & ~3) | 2;      // shuffle source: lane holding col 12

    for (int g = blockIdx.x; g < NTILES; g += gridDim.x) {
        // ================= QKV GEMM -> swizzled row-major head blocks ==========
        {
            u32 af[2][6][4];
            #pragma unroll
            for (int wd = 0; wd < 2; wd++) {
                const float* xr = x + ((size_t)g * 64 + (wp * 2 + wd) * 16 + gi) * 96;
                #pragma unroll
                for (int ks = 0; ks < 6; ks++) {
                    float2 v0 = *(const float2*)(xr + ks * 16 + 2 * tg);
                    float2 v1 = *(const float2*)(xr + 768 + ks * 16 + 2 * tg);
                    float2 v2 = *(const float2*)(xr + ks * 16 + 2 * tg + 8);
                    float2 v3 = *(const float2*)(xr + 768 + ks * 16 + 2 * tg + 8);
                    af[wd][ks][0] = p16(v0.x, v0.y);
                    af[wd][ks][1] = p16(v1.x, v1.y);
                    af[wd][ks][2] = p16(v2.x, v2.y);
                    af[wd][ks][3] = p16(v3.x, v3.y);
                }
            }
            // refresh pad slots of heads 0,1 (trampled by last tile's AF)
            for (int i = t; i < 768; i += 128) {
                int win = i / 192, r = i % 192;
                int h = r / 96, r2 = r % 96, sec = r2 >> 5, r3 = r2 & 31;
                int row = r3 >> 1, slot = 6 + (r3 & 1);
                QF[win * 3072 + h * 384 + sec * 128 + row * 8 + (slot ^ (row & 4))] =
                    (sec == 2 && slot == 6) ? 0x00003C00u : 0u;
            }
            #pragma unroll 2
            for (int j = 0; j < 18; j++) {
                const int cq = cs * 18 + j;
                float2 bb = *(const float2*)&BQs[cq * 8 + 2 * tg];
                float c[2][4];
                c[0][0] = bb.x; c[0][1] = bb.y; c[0][2] = bb.x; c[0][3] = bb.y;
                c[1][0] = bb.x; c[1][1] = bb.y; c[1][2] = bb.x; c[1][3] = bb.y;
                const u32* bp = PQG + (size_t)cq * 384 + ln * 4;
                #pragma unroll
                for (int ks2 = 0; ks2 < 3; ks2++) {
                    uint4 bv = __ldg((const uint4*)(bp + ks2 * 128));
                    mma16(c[0][0], c[0][1], c[0][2], c[0][3],
                          af[0][2*ks2][0], af[0][2*ks2][1], af[0][2*ks2][2], af[0][2*ks2][3],
                          bv.x, bv.y);
                    mma16(c[1][0], c[1][1], c[1][2], c[1][3],
                          af[1][2*ks2][0], af[1][2*ks2][1], af[1][2*ks2][2], af[1][2*ks2][3],
                          bv.x, bv.y);
                    mma16(c[0][0], c[0][1], c[0][2], c[0][3],
                          af[0][2*ks2+1][0], af[0][2*ks2+1][1], af[0][2*ks2+1][2], af[0][2*ks2+1][3],
                          bv.z, bv.w);
                    mma16(c[1][0], c[1][1], c[1][2], c[1][3],
                          af[1][2*ks2+1][0], af[1][2*ks2+1][1], af[1][2*ks2+1][2], af[1][2*ks2+1][3],
                          bv.z, bv.w);
                }
                int col = cq * 8 + 2 * tg;
                int sec = (col >= 192) ? 2 : (col >= 96 ? 1 : 0);
                int rem = col - sec * 96;
                int h   = (rem * 171) >> 11;
                int d   = rem - h * 12;
                float vs = (sec == 0) ? SCALE : 1.f;     // fold softmax scale into Q
                int base = h * 384 + sec * 128 + gi * 8 + (((d >> 1)) ^ xgi);
                #pragma unroll
                for (int wd = 0; wd < 2; wd++) {
                    int wb = (wp * 2 + wd) * 3072;
                    QF[wb + base]      = p16(c[wd][0] * vs, c[wd][1] * vs);
                    QF[wb + base + 64] = p16(c[wd][2] * vs, c[wd][3] * vs);  // row gi+8
                }
            }
        }
        __syncthreads();

        // ================= Attention: ldmatrix + mma, sum via ones-col =========
        {
            const int aw = wid;                    // warp = window
            const int wb = aw * 3072;
            u32 hbase = sb + (u32)wb * 4;          // byte base of head 0 block
            const float* mrow = mask + (size_t)((g * 4 + aw) % L_DIM) * 256;
            float2 mk00 = *(const float2*)(mrow + gi * 16 + 2 * tg);
            float2 mk01 = *(const float2*)(mrow + gi * 16 + 8 + 2 * tg);
            float2 mk10 = *(const float2*)(mrow + (gi + 8) * 16 + 2 * tg);
            float2 mk11 = *(const float2*)(mrow + (gi + 8) * 16 + 8 + 2 * tg);
            const __half2* RB2 = (const __half2*)RBH;

            #pragma unroll 2
            for (int h = 0; h < 8; h++) {
                u32 qa0, qa1, qa2, qa3, k0, k1, k2, k3, v0, v1, v2, v3;
                ldsm4 (qa0, qa1, qa2, qa3, hbase + offQ);
                ldsm4 (k0, k1, k2, k3, hbase + offK);
                ldsm4t(v0, v1, v2, v3, hbase + offV);

                float2 b00 = __half22float2(__ldg(RB2 + h * 128 + gi * 8 + tg));
                float2 b01 = __half22float2(__ldg(RB2 + h * 128 + gi * 8 + tg + 4));
                float2 b10 = __half22float2(__ldg(RB2 + h * 128 + (gi + 8) * 8 + tg));
                float2 b11 = __half22float2(__ldg(RB2 + h * 128 + (gi + 8) * 8 + tg + 4));

                float c00 = mk00.x + b00.x, c01 = mk00.y + b00.y;
                float c02 = mk10.x + b10.x, c03 = mk10.y + b10.y;
                float c10 = mk01.x + b01.x, c11 = mk01.y + b01.y;
                float c12 = mk11.x + b11.x, c13 = mk11.y + b11.y;
                mma16(c00, c01, c02, c03, qa0, qa1, qa2, qa3, k0, k1);
                mma16(c10, c11, c12, c13, qa0, qa1, qa2, qa3, k2, k3);

                // no max-subtraction: |scores| <= ~6 (mask-dominated), exp is safe
                float e00 = __expf(c00), e01 = __expf(c01);
                float e02 = __expf(c02), e03 = __expf(c03);
                float e10 = __expf(c10), e11 = __expf(c11);
                float e12 = __expf(c12), e13 = __expf(c13);

                u32 pa0 = p16(e00, e01), pa1 = p16(e02, e03);
                u32 pa2 = p16(e10, e11), pa3 = p16(e12, e13);

                float o00 = 0, o01 = 0, o02 = 0, o03 = 0;
                float o10 = 0, o11 = 0, o12 = 0, o13 = 0;
                mma16(o00, o01, o02, o03, pa0, pa1, pa2, pa3, v0, v1);
                mma16(o10, o11, o12, o13, pa0, pa1, pa2, pa3, v2, v3);

                // row sums arrive at col 12 (ones column) -> lane tg=2 regs o10/o12
                float slo = __shfl_sync(0xffffffffu, o10, srcln);
                float shi = __shfl_sync(0xffffffffu, o12, srcln);
                float invlo = __fdividef(1.f, slo);
                float invhi = __fdividef(1.f, shi);

                // store attn-out in paired proj-A-frag order (AF aliases QF prefix)
                int col0 = h * 12 + 2 * tg;
                int ks0  = col0 >> 4;
                int p0   = (col0 >> 3) & 1;
                int lt0  = gi * 4 + ((col0 & 7) >> 1);
                uint2 sv0;
                sv0.x = p16(o00 * invlo, o01 * invlo);
                sv0.y = p16(o02 * invhi, o03 * invhi);
                *(uint2*)&QF[wb + ks0 * 128 + p0 * 64 + lt0 * 2] = sv0;
                if (tg < 2) {
                    int col1 = col0 + 8;
                    int ks1  = col1 >> 4;
                    int p1   = (col1 >> 3) & 1;
                    int lt1  = gi * 4 + ((col1 & 7) >> 1);
                    uint2 sv1;
                    sv1.x = p16(o10 * invlo, o11 * invlo);
                    sv1.y = p16(o12 * invhi, o13 * invhi);
                    *(uint2*)&QF[wb + ks1 * 128 + p1 * 64 + lt1 * 2] = sv1;
                }
                hbase += 1536;
            }
        }
        __syncthreads();

        // ================= Proj GEMM (A frags as LDS.64 pairs from AF) ==========
        {
            u32 pf[2][6][4];
            #pragma unroll
            for (int wd = 0; wd < 2; wd++) {
                const int wb = (wp * 2 + wd) * 3072;
                #pragma unroll
                for (int ks = 0; ks < 6; ks++) {
                    uint2 L0 = *(const uint2*)&QF[wb + ks * 128 + ln * 2];
                    uint2 L1 = *(const uint2*)&QF[wb + ks * 128 + 64 + ln * 2];
                    pf[wd][ks][0] = L0.x; pf[wd][ks][1] = L0.y;
                    pf[wd][ks][2] = L1.x; pf[wd][ks][3] = L1.y;
                }
            }
            #pragma unroll 2
            for (int j = 0; j < 6; j++) {
                const int cq = cs * 6 + j;
                float2 bb = *(const float2*)&BPs[cq * 8 + 2 * tg];
                float c[2][4];
                c[0][0] = bb.x; c[0][1] = bb.y; c[0][2] = bb.x; c[0][3] = bb.y;
                c[1][0] = bb.x; c[1][1] = bb.y; c[1][2] = bb.x; c[1][3] = bb.y;
                const u32* bp = PRJG + (size_t)cq * 384 + ln * 4;
                #pragma unroll
                for (int ks2 = 0; ks2 < 3; ks2++) {
                    uint4 bv = __ldg((const uint4*)(bp + ks2 * 128));
                    mma16(c[0][0], c[0][1], c[0][2], c[0][3],
                          pf[0][2*ks2][0], pf[0][2*ks2][1], pf[0][2*ks2][2], pf[0][2*ks2][3],
                          bv.x, bv.y);
                    mma16(c[1][0], c[1][1], c[1][2], c[1][3],
                          pf[1][2*ks2][0], pf[1][2*ks2][1], pf[1][2*ks2][2], pf[1][2*ks2][3],
                          bv.x, bv.y);
                    mma16(c[0][0], c[0][1], c[0][2], c[0][3],
                          pf[0][2*ks2+1][0], pf[0][2*ks2+1][1], pf[0][2*ks2+1][2], pf[0][2*ks2+1][3],
                          bv.z, bv.w);
                    mma16(c[1][0], c[1][1], c[1][2], c[1][3],
                          pf[1][2*ks2+1][0], pf[1][2*ks2+1][1], pf[1][2*ks2+1][2], pf[1][2*ks2+1][3],
                          bv.z, bv.w);
                }
                #pragma unroll
                for (int wd = 0; wd < 2; wd++) {
                    float* og = out + ((size_t)g * 64 + (wp * 2 + wd) * 16 + gi) * 96
                                    + cq * 8 + 2 * tg;
                    *(float2*)og            = make_float2(c[wd][0], c[wd][1]);
                    *(float2*)(og + 8 * 96) = make_float2(c[wd][2], c[wd][3]);
                }
            }
        }
        __syncthreads();   // QF reuse by next tile
    }
}

extern "C" void kernel_launch(void* const* d_in, const int* in_sizes, int n_in,
                              void* d_out, int out_size)
{
    const float* x          = (const float*)d_in[0];
    const float* mask       = (const float*)d_in[1];
    const float* qkv_w      = (const float*)d_in[2];
    const float* qkv_b      = (const float*)d_in[3];
    const float* proj_w     = (const float*)d_in[4];
    const float* proj_b     = (const float*)d_in[5];
    const float* bias_table = (const float*)d_in[6];
    float* out = (float*)d_out;

    int sms = 148;
    cudaDeviceGetAttribute(&sms, cudaDevAttrMultiProcessorCount, 0);
    cudaFuncSetAttribute(win_attn_kernel,
                         cudaFuncAttributeMaxDynamicSharedMemorySize, SMEM_BYTES);

    win_attn_kernel<<<4 * sms, 128, SMEM_BYTES>>>(x, mask, qkv_w, qkv_b,
                                                  proj_w, proj_b, bias_table, out);
}